// round 9
// baseline (speedup 1.0000x reference)
#include <cuda_runtime.h>
#include <cuda_bf16.h>
#include <cstdint>
#include <math.h>

// Problem constants
#define NB 4
#define SEQ 1024
#define CH 1024
#define NH 16
#define DH 64
#define NROWS (NB * SEQ)
#define FFNDIM (4 * CH)
#define ASCALE 0.03125f
#define LNEPS 1e-5f

typedef __nv_bfloat16 bf16;
typedef __nv_bfloat162 bf162;

// ---------------- scratch ----------------------------------------------------
__device__ float g_buf[NB * 6 * CH];
__device__ float x1_buf[(size_t)NROWS * CH];

__device__ bf16 wq_h[CH * CH], wq_l[CH * CH];
__device__ bf16 wk_h[CH * CH], wk_l[CH * CH];
__device__ bf16 wv_h[CH * CH], wv_l[CH * CH];
__device__ bf16 wo_h[CH * CH], wo_l[CH * CH];
__device__ bf16 w1_h[(size_t)FFNDIM * CH], w1_l[(size_t)FFNDIM * CH];
__device__ bf16 w2_h[(size_t)CH * FFNDIM], w2_l[(size_t)CH * FFNDIM];
__device__ bf16 ctx_h[(size_t)NROWS * CH], ctx_l[(size_t)NROWS * CH];
__device__ bf16 mod_h[(size_t)NROWS * CH], mod_l[(size_t)NROWS * CH];
__device__ bf16 ao_h[(size_t)NROWS * CH], ao_l[(size_t)NROWS * CH];
__device__ bf16 hb_h[(size_t)NROWS * FFNDIM], hb_l[(size_t)NROWS * FFNDIM];
__device__ bf16 q_h[(size_t)NROWS * CH], q_l[(size_t)NROWS * CH];
__device__ bf16 k_h[(size_t)NROWS * CH], k_l[(size_t)NROWS * CH];
__device__ bf16 v_h[(size_t)NROWS * CH], v_l[(size_t)NROWS * CH];

// ---------------- PTX helpers ------------------------------------------------
__device__ __forceinline__ uint32_t smem_u32(const void* p) {
    uint32_t a;
    asm("{ .reg .u64 t; cvta.to.shared.u64 t, %1; cvt.u32.u64 %0, t; }"
        : "=r"(a) : "l"(p));
    return a;
}
__device__ __forceinline__ void cp_async16(uint32_t sa, const void* ga) {
    asm volatile("cp.async.cg.shared.global [%0], [%1], 16;"
                 :: "r"(sa), "l"(ga) : "memory");
}
#define CP_COMMIT() asm volatile("cp.async.commit_group;" ::: "memory")
#define CP_WAIT(n)  asm volatile("cp.async.wait_group %0;" :: "n"(n) : "memory")

#define LDSM4(r0, r1, r2, r3, addr) \
    asm volatile("ldmatrix.sync.aligned.m8n8.x4.shared.b16 {%0,%1,%2,%3}, [%4];" \
                 : "=r"(r0), "=r"(r1), "=r"(r2), "=r"(r3) : "r"(addr))

#define LDSM4T(r0, r1, r2, r3, addr) \
    asm volatile("ldmatrix.sync.aligned.m8n8.x4.trans.shared.b16 {%0,%1,%2,%3}, [%4];" \
                 : "=r"(r0), "=r"(r1), "=r"(r2), "=r"(r3) : "r"(addr))

#define MMA_BF16(c, a, b) \
    asm volatile( \
        "mma.sync.aligned.m16n8k16.row.col.f32.bf16.bf16.f32 " \
        "{%0,%1,%2,%3}, {%4,%5,%6,%7}, {%8,%9}, {%0,%1,%2,%3};" \
        : "+f"((c)[0]), "+f"((c)[1]), "+f"((c)[2]), "+f"((c)[3]) \
        : "r"((a)[0]), "r"((a)[1]), "r"((a)[2]), "r"((a)[3]), \
          "r"((b)[0]), "r"((b)[1]))

#define MMA_BF16_2(c, a, b0, b1) \
    asm volatile( \
        "mma.sync.aligned.m16n8k16.row.col.f32.bf16.bf16.f32 " \
        "{%0,%1,%2,%3}, {%4,%5,%6,%7}, {%8,%9}, {%0,%1,%2,%3};" \
        : "+f"((c)[0]), "+f"((c)[1]), "+f"((c)[2]), "+f"((c)[3]) \
        : "r"((a)[0]), "r"((a)[1]), "r"((a)[2]), "r"((a)[3]), \
          "r"(b0), "r"(b1))

// GEMM tiles: [128 rows][32 bf16 = 64B], 4 groups of 16B
__device__ __forceinline__ uint32_t sw_off(int row, int g) {
    return (uint32_t)(row * 64 + (((g ^ (row >> 1)) & 3) << 4));
}
// Attention tiles: [rows][64 bf16 = 128B], 8 groups of 16B
__device__ __forceinline__ uint32_t sw128(int row, int g) {
    return (uint32_t)(row * 128 + (((g ^ row) & 7) << 4));
}

__device__ __forceinline__ void split_f(float x, bf16& h, bf16& l) {
    h = __float2bfloat16_rn(x);
    l = __float2bfloat16_rn(x - __bfloat162float(h));
}
__device__ __forceinline__ uint32_t pack_bf2(float a, float b) {
    bf162 t = __floats2bfloat162_rn(a, b);
    return *(uint32_t*)&t;
}

// ---------------- g = ada_gss + cond_BD -------------------------------------
__global__ void add_params_kernel(const float* __restrict__ ada,
                                  const float* __restrict__ cond) {
    int i = blockIdx.x * blockDim.x + threadIdx.x;
    if (i < NB * 6 * CH) g_buf[i] = ada[i % (6 * CH)] + cond[i];
}

// ---------------- fp32 -> (bf16 hi, bf16 lo) split (4x float4 / thread) -----
__device__ __forceinline__ void split_store(const float* __restrict__ src,
                                            bf16* __restrict__ hi,
                                            bf16* __restrict__ lo, int i) {
    float4 v = ((const float4*)src)[i];
    bf16 h0, h1, h2, h3, l0, l1, l2, l3;
    split_f(v.x, h0, l0); split_f(v.y, h1, l1);
    split_f(v.z, h2, l2); split_f(v.w, h3, l3);
    bf162* hp = (bf162*)(hi + (size_t)i * 4);
    bf162* lp = (bf162*)(lo + (size_t)i * 4);
    hp[0] = bf162(h0, h1); hp[1] = bf162(h2, h3);
    lp[0] = bf162(l0, l1); lp[1] = bf162(l2, l3);
}

__global__ void split_kernel(const float* __restrict__ src,
                             bf16* __restrict__ hi, bf16* __restrict__ lo,
                             int n4) {
    int i = blockIdx.x * 1024 + threadIdx.x;
    #pragma unroll
    for (int c = 0; c < 4; c++, i += 256)
        if (i < n4) split_store(src, hi, lo, i);
}

// three splits in one launch (blockIdx.y selects tensor)
struct Split3Args {
    const float* src[3];
    bf16* hi[3];
    bf16* lo[3];
};
__global__ void split3_kernel(Split3Args a, int n4) {
    int z = blockIdx.y;
    int i = blockIdx.x * 1024 + threadIdx.x;
    #pragma unroll
    for (int c = 0; c < 4; c++, i += 256)
        if (i < n4) split_store(a.src[z], a.hi[z], a.lo[z], i);
}

// ---------------- LayerNorm + AdaLN modulate -> hi/lo planes ----------------
__global__ void ln_mod_kernel(const float* __restrict__ X,
                              bf16* __restrict__ Oh, bf16* __restrict__ Ol,
                              int si, int hi) {
    int row = blockIdx.x;
    int b = row >> 10;
    int t = threadIdx.x;
    const float4* xr = (const float4*)(X + (size_t)row * CH);
    float4 v = xr[t];

    __shared__ float red[8];
    float s = v.x + v.y + v.z + v.w;
    #pragma unroll
    for (int o = 16; o; o >>= 1) s += __shfl_xor_sync(0xffffffffu, s, o);
    if ((t & 31) == 0) red[t >> 5] = s;
    __syncthreads();
    float tot = 0.f;
    #pragma unroll
    for (int w = 0; w < 8; w++) tot += red[w];
    float mean = tot * (1.0f / CH);

    float dx = v.x - mean, dy = v.y - mean, dz = v.z - mean, dw = v.w - mean;
    float s2 = dx * dx + dy * dy + dz * dz + dw * dw;
    #pragma unroll
    for (int o = 16; o; o >>= 1) s2 += __shfl_xor_sync(0xffffffffu, s2, o);
    __syncthreads();
    if ((t & 31) == 0) red[t >> 5] = s2;
    __syncthreads();
    float tot2 = 0.f;
    #pragma unroll
    for (int w = 0; w < 8; w++) tot2 += red[w];
    float rstd = rsqrtf(tot2 * (1.0f / CH) + LNEPS);

    const float* gb = g_buf + (size_t)b * 6 * CH;
    float4 sc = *(const float4*)(gb + si * CH + t * 4);
    float4 sh = *(const float4*)(gb + hi * CH + t * 4);
    float m0 = dx * rstd * (1.0f + sc.x) + sh.x;
    float m1 = dy * rstd * (1.0f + sc.y) + sh.y;
    float m2 = dz * rstd * (1.0f + sc.z) + sh.z;
    float m3 = dw * rstd * (1.0f + sc.w) + sh.w;

    bf16 h0, h1, h2, h3, l0, l1, l2, l3;
    split_f(m0, h0, l0); split_f(m1, h1, l1);
    split_f(m2, h2, l2); split_f(m3, h3, l3);
    size_t base = (size_t)row * CH + t * 4;
    bf162* hp = (bf162*)(Oh + base);
    bf162* lp = (bf162*)(Ol + base);
    hp[0] = bf162(h0, h1); hp[1] = bf162(h2, h3);
    lp[0] = bf162(l0, l1); lp[1] = bf162(l2, l3);
}

__device__ __forceinline__ float gelu_tanh(float u) {
    float z = 0.7978845608028654f * (u + 0.044715f * u * u * u);
    float e = __expf(-2.0f * z);
    return u / (1.0f + e);
}

// ---------------- 3xbf16 mma.sync GEMM core (R8-proven: 2 CTA/SM) -----------
#define BKB 32
#define GSTAGES 3
#define PLANE_BYTES 8192
#define STAGE_BYTES (4 * PLANE_BYTES)
#define GEMM_SMEM (GSTAGES * STAGE_BYTES)

// MODE 0: Yf = dot
// MODE 1/3: Yf = xres + (dot + bias[n]) * gam[b*6C + n]
// MODE 2: (Yh, Yl) = split(gelu(dot + bias[n]))
// MODE 4: (Yh, Yl) = split(dot)
template <int MODE>
__device__ __forceinline__ void gemm_core(
        const bf16* __restrict__ Ah, const bf16* __restrict__ Al,
        const bf16* __restrict__ Bh, const bf16* __restrict__ Bl,
        float* __restrict__ Yf, bf16* __restrict__ Yh, bf16* __restrict__ Yl,
        int N, int K,
        const float* __restrict__ bias, const float* __restrict__ gam,
        const float* __restrict__ xres,
        uint32_t smb, int bm, int bn) {
    int tid = threadIdx.x;
    int lane = tid & 31, wid = tid >> 5;
    int wm = wid >> 2;
    int wn = wid & 3;
    const int NC = K / BKB;

    auto issue = [&](int c, int st) {
        uint32_t s0 = smb + st * STAGE_BYTES;
        #pragma unroll
        for (int half = 0; half < 2; half++) {
            int i = half * 256 + tid;
            int row = i >> 2, g = i & 3;
            uint32_t so = sw_off(row, g);
            size_t aoff = (size_t)(bm + row) * K + c * BKB + g * 8;
            size_t boff = (size_t)(bn + row) * K + c * BKB + g * 8;
            cp_async16(s0 + so, Ah + aoff);
            cp_async16(s0 + PLANE_BYTES + so, Al + aoff);
            cp_async16(s0 + 2 * PLANE_BYTES + so, Bh + boff);
            cp_async16(s0 + 3 * PLANE_BYTES + so, Bl + boff);
        }
        CP_COMMIT();
    };

    issue(0, 0);
    issue(1, 1);

    float c[16][4];
    #pragma unroll
    for (int i = 0; i < 16; i++)
        #pragma unroll
        for (int j = 0; j < 4; j++) c[i][j] = 0.f;

    int a_row_base = wm * 64 + ((lane >> 3) & 1) * 8 + (lane & 7);
    int a_g_base = (lane >> 4);
    int b_row_base = wn * 32 + ((lane >> 4) & 1) * 8 + (lane & 7);
    int b_g_base = ((lane >> 3) & 1);

    int sidx = 0, pidx = 2;
    for (int kt = 0; kt < NC; kt++) {
        if (kt + 1 < NC) { CP_WAIT(1); } else { CP_WAIT(0); }
        __syncthreads();
        if (kt + 2 < NC) issue(kt + 2, pidx);

        uint32_t sAh = smb + sidx * STAGE_BYTES;
        uint32_t sAl = sAh + PLANE_BYTES;
        uint32_t sBh = sAh + 2 * PLANE_BYTES;
        uint32_t sBl = sAh + 3 * PLANE_BYTES;

        #pragma unroll
        for (int ks = 0; ks < 2; ks++) {
            int ag = ks * 2 + a_g_base;
            int bg = ks * 2 + b_g_base;
            uint32_t bh[4][2], bl[4][2];
            #pragma unroll
            for (int tp = 0; tp < 2; tp++) {
                uint32_t so = sw_off(b_row_base + tp * 16, bg);
                uint32_t r0, r1, r2, r3;
                LDSM4(r0, r1, r2, r3, sBh + so);
                bh[tp * 2][0] = r0;     bh[tp * 2][1] = r1;
                bh[tp * 2 + 1][0] = r2; bh[tp * 2 + 1][1] = r3;
                LDSM4(r0, r1, r2, r3, sBl + so);
                bl[tp * 2][0] = r0;     bl[tp * 2][1] = r1;
                bl[tp * 2 + 1][0] = r2; bl[tp * 2 + 1][1] = r3;
            }
            #pragma unroll
            for (int tm = 0; tm < 4; tm++) {
                uint32_t ah[4], al[4];
                uint32_t so = sw_off(a_row_base + tm * 16, ag);
                LDSM4(ah[0], ah[1], ah[2], ah[3], sAh + so);
                LDSM4(al[0], al[1], al[2], al[3], sAl + so);
                #pragma unroll
                for (int tn = 0; tn < 4; tn++) {
                    MMA_BF16(c[tm * 4 + tn], ah, bh[tn]);
                    MMA_BF16(c[tm * 4 + tn], ah, bl[tn]);
                    MMA_BF16(c[tm * 4 + tn], al, bh[tn]);
                }
            }
        }
        sidx = (sidx + 1 == GSTAGES) ? 0 : sidx + 1;
        pidx = (pidx + 1 == GSTAGES) ? 0 : pidx + 1;
    }

    #pragma unroll
    for (int tm = 0; tm < 4; tm++) {
        #pragma unroll
        for (int half = 0; half < 2; half++) {
            int row = bm + wm * 64 + tm * 16 + (lane >> 2) + half * 8;
            size_t rbase = (size_t)row * N;
            int bb = row >> 10;
            #pragma unroll
            for (int tn = 0; tn < 4; tn++) {
                int col = bn + wn * 32 + tn * 8 + (lane & 3) * 2;
                float d0 = c[tm * 4 + tn][half * 2 + 0];
                float d1 = c[tm * 4 + tn][half * 2 + 1];
                if (MODE == 0) {
                    *(float2*)(Yf + rbase + col) = make_float2(d0, d1);
                } else if (MODE == 4) {
                    bf16 h0, h1, l0, l1;
                    split_f(d0, h0, l0);
                    split_f(d1, h1, l1);
                    *(bf162*)(Yh + rbase + col) = bf162(h0, h1);
                    *(bf162*)(Yl + rbase + col) = bf162(l0, l1);
                } else if (MODE == 2) {
                    float2 bi = *(const float2*)(bias + col);
                    d0 = gelu_tanh(d0 + bi.x);
                    d1 = gelu_tanh(d1 + bi.y);
                    bf16 h0, h1, l0, l1;
                    split_f(d0, h0, l0);
                    split_f(d1, h1, l1);
                    *(bf162*)(Yh + rbase + col) = bf162(h0, h1);
                    *(bf162*)(Yl + rbase + col) = bf162(l0, l1);
                } else {
                    float2 bi = *(const float2*)(bias + col);
                    d0 += bi.x; d1 += bi.y;
                    float2 gv = *(const float2*)(gam + (size_t)bb * 6 * CH + col);
                    float2 xr = *(const float2*)(xres + rbase + col);
                    *(float2*)(Yf + rbase + col) =
                        make_float2(xr.x + d0 * gv.x, xr.y + d1 * gv.y);
                }
            }
        }
    }
}

template <int MODE>
__global__ void __launch_bounds__(256, 2)
gemm_bf3(const bf16* __restrict__ Ah, const bf16* __restrict__ Al,
         const bf16* __restrict__ Bh, const bf16* __restrict__ Bl,
         float* __restrict__ Yf, bf16* __restrict__ Yh, bf16* __restrict__ Yl,
         int M, int N, int K,
         const float* __restrict__ bias, const float* __restrict__ gam,
         const float* __restrict__ xres) {
    extern __shared__ char smraw[];
    gemm_core<MODE>(Ah, Al, Bh, Bl, Yf, Yh, Yl, N, K, bias, gam, xres,
                    smem_u32(smraw), blockIdx.y * 128, blockIdx.x * 128);
}

// merged Q/K/V projection: blockIdx.z selects the (A, B, Y) triple
struct QkvArgs {
    const bf16 *ah[3], *al[3], *bh[3], *bl[3];
    bf16 *yh[3], *yl[3];
};
__global__ void __launch_bounds__(256, 2)
gemm_qkv(QkvArgs a) {
    extern __shared__ char smraw[];
    int z = blockIdx.z;
    gemm_core<4>(a.ah[z], a.al[z], a.bh[z], a.bl[z],
                 nullptr, a.yh[z], a.yl[z], CH, CH,
                 nullptr, nullptr, nullptr,
                 smem_u32(smraw), blockIdx.y * 128, blockIdx.x * 128);
}

// ---------------- FA2-style attention, 128 q-rows / 8 warps per CTA ---------
// smem: Q hi/lo [128][64] (32KB) + 2 stages x (Kh,Kl,Vh,Vl [64][64]) (64KB)
#define ATT_SMEM (32768 + 2 * 32768)

__global__ void __launch_bounds__(256)
attn_mma(const bf16* __restrict__ Qh, const bf16* __restrict__ Ql,
         const bf16* __restrict__ Kh, const bf16* __restrict__ Kl,
         const bf16* __restrict__ Vh, const bf16* __restrict__ Vl,
         const float* __restrict__ bias,
         bf16* __restrict__ Oh, bf16* __restrict__ Ol) {
    extern __shared__ char smraw[];
    uint32_t smb = smem_u32(smraw);
    int tid = threadIdx.x;
    int lane = tid & 31, w = tid >> 5;      // 8 warps, 16 q-rows each
    int bh = blockIdx.x;
    int b = bh >> 4, h = bh & 15;
    int q0 = blockIdx.y * 128;

    // Q tiles: 2 planes x [128][64] (16KB each)
    {
        const bf16* qp[2] = {Qh, Ql};
        #pragma unroll
        for (int it = 0; it < 8; it++) {
            int pl = it >> 2;
            int row = (it & 3) * 32 + (tid >> 3);   // 0..127
            int g = tid & 7;
            cp_async16(smb + pl * 16384 + sw128(row, g),
                       qp[pl] + (size_t)(b * SEQ + q0 + row) * CH + h * DH + g * 8);
        }
    }
    // K/V tile kt -> stage kt&1 (4 planes x [64][64])
    auto issue_tile = [&](int kt) {
        uint32_t st = smb + 32768 + (kt & 1) * 32768;
        const bf16* pp[4] = {Kh, Kl, Vh, Vl};
        #pragma unroll
        for (int it = 0; it < 8; it++) {
            int pl = it >> 1;
            int row = (it & 1) * 32 + (tid >> 3);   // 0..63
            int g = tid & 7;
            cp_async16(st + pl * 8192 + sw128(row, g),
                       pp[pl] + (size_t)(b * SEQ + kt * 64 + row) * CH + h * DH + g * 8);
        }
    };
    issue_tile(0);
    CP_COMMIT();
    CP_WAIT(0);
    __syncthreads();

    uint32_t qhf[4][4], qlf[4][4];
    {
        int qrow = w * 16 + (lane & 15);            // 0..127
        #pragma unroll
        for (int ks = 0; ks < 4; ks++) {
            uint32_t so = sw128(qrow, ks * 2 + (lane >> 4));
            LDSM4(qhf[ks][0], qhf[ks][1], qhf[ks][2], qhf[ks][3], smb + so);
            LDSM4(qlf[ks][0], qlf[ks][1], qlf[ks][2], qlf[ks][3], smb + 16384 + so);
        }
    }

    float o[8][4];
    #pragma unroll
    for (int n = 0; n < 8; n++)
        #pragma unroll
        for (int j = 0; j < 4; j++) o[n][j] = 0.f;
    float miA = -1e30f, miB = -1e30f, liA = 0.f, liB = 0.f;

    const float* bp0 = bias +
        ((size_t)(b * NH + h) * SEQ + q0 + w * 16 + (lane >> 2)) * SEQ + (lane & 3) * 2;

    for (int kt = 0; kt < 16; kt++) {
        if (kt + 1 < 16) { issue_tile(kt + 1); CP_COMMIT(); }

        uint32_t sKh = smb + 32768 + (kt & 1) * 32768;
        uint32_t sKl = sKh + 8192;
        uint32_t sVh = sKh + 16384;
        uint32_t sVl = sKh + 24576;

        float s[8][4];
        #pragma unroll
        for (int n = 0; n < 8; n++)
            #pragma unroll
            for (int j = 0; j < 4; j++) s[n][j] = 0.f;

        int krow_base = ((lane >> 4) & 1) * 8 + (lane & 7);
        int kg_base = (lane >> 3) & 1;
        #pragma unroll
        for (int ks = 0; ks < 4; ks++) {
            int kg = ks * 2 + kg_base;
            #pragma unroll
            for (int np = 0; np < 4; np++) {
                uint32_t so = sw128(np * 16 + krow_base, kg);
                uint32_t h0, h1, h2, h3, l0, l1, l2, l3;
                LDSM4(h0, h1, h2, h3, sKh + so);
                LDSM4(l0, l1, l2, l3, sKl + so);
                MMA_BF16_2(s[np * 2], qhf[ks], h0, h1);
                MMA_BF16_2(s[np * 2], qlf[ks], h0, h1);
                MMA_BF16_2(s[np * 2], qhf[ks], l0, l1);
                MMA_BF16_2(s[np * 2 + 1], qhf[ks], h2, h3);
                MMA_BF16_2(s[np * 2 + 1], qlf[ks], h2, h3);
                MMA_BF16_2(s[np * 2 + 1], qhf[ks], l2, l3);
            }
        }

        const float* bp = bp0 + kt * 64;
        #pragma unroll
        for (int n = 0; n < 8; n++) {
            float2 bA = *(const float2*)(bp + n * 8);
            float2 bB = *(const float2*)(bp + (size_t)8 * SEQ + n * 8);
            s[n][0] = fmaf(s[n][0], ASCALE, bA.x);
            s[n][1] = fmaf(s[n][1], ASCALE, bA.y);
            s[n][2] = fmaf(s[n][2], ASCALE, bB.x);
            s[n][3] = fmaf(s[n][3], ASCALE, bB.y);
        }

        float mA = -1e30f, mB = -1e30f;
        #pragma unroll
        for (int n = 0; n < 8; n++) {
            mA = fmaxf(mA, fmaxf(s[n][0], s[n][1]));
            mB = fmaxf(mB, fmaxf(s[n][2], s[n][3]));
        }
        mA = fmaxf(mA, __shfl_xor_sync(0xffffffffu, mA, 1));
        mA = fmaxf(mA, __shfl_xor_sync(0xffffffffu, mA, 2));
        mB = fmaxf(mB, __shfl_xor_sync(0xffffffffu, mB, 1));
        mB = fmaxf(mB, __shfl_xor_sync(0xffffffffu, mB, 2));
        float mnA = fmaxf(miA, mA), mnB = fmaxf(miB, mB);
        float corrA = __expf(miA - mnA), corrB = __expf(miB - mnB);
        miA = mnA; miB = mnB;
        float rsA = 0.f, rsB = 0.f;
        #pragma unroll
        for (int n = 0; n < 8; n++) {
            s[n][0] = __expf(s[n][0] - mnA);
            s[n][1] = __expf(s[n][1] - mnA);
            s[n][2] = __expf(s[n][2] - mnB);
            s[n][3] = __expf(s[n][3] - mnB);
            rsA += s[n][0] + s[n][1];
            rsB += s[n][2] + s[n][3];
        }
        rsA += __shfl_xor_sync(0xffffffffu, rsA, 1);
        rsA += __shfl_xor_sync(0xffffffffu, rsA, 2);
        rsB += __shfl_xor_sync(0xffffffffu, rsB, 1);
        rsB += __shfl_xor_sync(0xffffffffu, rsB, 2);
        liA = liA * corrA + rsA;
        liB = liB * corrB + rsB;
        #pragma unroll
        for (int n = 0; n < 8; n++) {
            o[n][0] *= corrA; o[n][1] *= corrA;
            o[n][2] *= corrB; o[n][3] *= corrB;
        }

        int vrow_base = ((lane >> 3) & 1) * 8 + (lane & 7);
        int vg_base = (lane >> 4) & 1;
        #pragma unroll
        for (int kk = 0; kk < 4; kk++) {
            uint32_t pah[4], pal[4];
            #pragma unroll
            for (int q = 0; q < 2; q++) {
                int nf = kk * 2 + q;
                float p0 = s[nf][0], p1 = s[nf][1], p2 = s[nf][2], p3 = s[nf][3];
                float h0 = __bfloat162float(__float2bfloat16_rn(p0));
                float h1 = __bfloat162float(__float2bfloat16_rn(p1));
                float h2 = __bfloat162float(__float2bfloat16_rn(p2));
                float h3 = __bfloat162float(__float2bfloat16_rn(p3));
                pah[q * 2 + 0] = pack_bf2(h0, h1);
                pah[q * 2 + 1] = pack_bf2(h2, h3);
                pal[q * 2 + 0] = pack_bf2(p0 - h0, p1 - h1);
                pal[q * 2 + 1] = pack_bf2(p2 - h2, p3 - h3);
            }
            #pragma unroll
            for (int dp = 0; dp < 4; dp++) {
                uint32_t so = sw128(kk * 16 + vrow_base, dp * 2 + vg_base);
                uint32_t r0, r1, r2, r3;
                LDSM4T(r0, r1, r2, r3, sVh + so);
                MMA_BF16_2(o[dp * 2], pah, r0, r1);
                MMA_BF16_2(o[dp * 2], pal, r0, r1);
                MMA_BF16_2(o[dp * 2 + 1], pah, r2, r3);
                MMA_BF16_2(o[dp * 2 + 1], pal, r2, r3);
                LDSM4T(r0, r1, r2, r3, sVl + so);
                MMA_BF16_2(o[dp * 2], pah, r0, r1);
                MMA_BF16_2(o[dp * 2 + 1], pah, r2, r3);
            }
        }

        if (kt + 1 < 16) { CP_WAIT(0); __syncthreads(); }
    }

    float invA = 1.0f / liA, invB = 1.0f / liB;
    size_t rowA = (size_t)(b * SEQ + q0 + w * 16 + (lane >> 2));
    #pragma unroll
    for (int n = 0; n < 8; n++) {
        int col = h * DH + n * 8 + (lane & 3) * 2;
        float f0 = o[n][0] * invA, f1 = o[n][1] * invA;
        float f2 = o[n][2] * invB, f3 = o[n][3] * invB;
        bf16 h0, h1, h2, h3, l0, l1, l2, l3;
        split_f(f0, h0, l0); split_f(f1, h1, l1);
        split_f(f2, h2, l2); split_f(f3, h3, l3);
        *(bf162*)(Oh + rowA * CH + col) = bf162(h0, h1);
        *(bf162*)(Ol + rowA * CH + col) = bf162(l0, l1);
        *(bf162*)(Oh + (rowA + 8) * CH + col) = bf162(h2, h3);
        *(bf162*)(Ol + (rowA + 8) * CH + col) = bf162(l2, l3);
    }
}

// ---------------- launch ------------------------------------------------------
extern "C" void kernel_launch(void* const* d_in, const int* in_sizes, int n_in,
                              void* d_out, int out_size) {
    const float* x         = (const float*)d_in[0];
    const float* context   = (const float*)d_in[1];
    const float* cond_BD   = (const float*)d_in[2];
    const float* attn_bias = (const float*)d_in[3];
    const float* ada_gss   = (const float*)d_in[4];
    const float* Wq        = (const float*)d_in[5];
    const float* Wk        = (const float*)d_in[6];
    const float* Wv        = (const float*)d_in[7];
    const float* Wo        = (const float*)d_in[8];
    const float* bo        = (const float*)d_in[9];
    const float* W1        = (const float*)d_in[10];
    const float* b1        = (const float*)d_in[11];
    const float* W2        = (const float*)d_in[12];
    const float* b2        = (const float*)d_in[13];
    float* out = (float*)d_out;

    float *g_p, *x1_p;
    cudaGetSymbolAddress((void**)&g_p, g_buf);
    cudaGetSymbolAddress((void**)&x1_p, x1_buf);

    bf16 *wqh, *wql, *wkh, *wkl, *wvh, *wvl, *woh, *wol;
    bf16 *w1h, *w1l, *w2h, *w2l, *ch_, *cl_, *mh, *ml, *aoh, *aol, *hh, *hl;
    bf16 *qh, *ql, *kh, *kl, *vh, *vl;
    cudaGetSymbolAddress((void**)&wqh, wq_h); cudaGetSymbolAddress((void**)&wql, wq_l);
    cudaGetSymbolAddress((void**)&wkh, wk_h); cudaGetSymbolAddress((void**)&wkl, wk_l);
    cudaGetSymbolAddress((void**)&wvh, wv_h); cudaGetSymbolAddress((void**)&wvl, wv_l);
    cudaGetSymbolAddress((void**)&woh, wo_h); cudaGetSymbolAddress((void**)&wol, wo_l);
    cudaGetSymbolAddress((void**)&w1h, w1_h); cudaGetSymbolAddress((void**)&w1l, w1_l);
    cudaGetSymbolAddress((void**)&w2h, w2_h); cudaGetSymbolAddress((void**)&w2l, w2_l);
    cudaGetSymbolAddress((void**)&ch_, ctx_h); cudaGetSymbolAddress((void**)&cl_, ctx_l);
    cudaGetSymbolAddress((void**)&mh, mod_h);  cudaGetSymbolAddress((void**)&ml, mod_l);
    cudaGetSymbolAddress((void**)&aoh, ao_h);  cudaGetSymbolAddress((void**)&aol, ao_l);
    cudaGetSymbolAddress((void**)&hh, hb_h);   cudaGetSymbolAddress((void**)&hl, hb_l);
    cudaGetSymbolAddress((void**)&qh, q_h);    cudaGetSymbolAddress((void**)&ql, q_l);
    cudaGetSymbolAddress((void**)&kh, k_h);    cudaGetSymbolAddress((void**)&kl, k_l);
    cudaGetSymbolAddress((void**)&vh, v_h);    cudaGetSymbolAddress((void**)&vl, v_l);

    cudaFuncSetAttribute(attn_mma,
                         cudaFuncAttributeMaxDynamicSharedMemorySize, ATT_SMEM);
    cudaFuncSetAttribute(gemm_qkv,
                         cudaFuncAttributeMaxDynamicSharedMemorySize, GEMM_SMEM);
    cudaFuncSetAttribute(gemm_bf3<1>,
                         cudaFuncAttributeMaxDynamicSharedMemorySize, GEMM_SMEM);
    cudaFuncSetAttribute(gemm_bf3<2>,
                         cudaFuncAttributeMaxDynamicSharedMemorySize, GEMM_SMEM);
    cudaFuncSetAttribute(gemm_bf3<3>,
                         cudaFuncAttributeMaxDynamicSharedMemorySize, GEMM_SMEM);

    add_params_kernel<<<24, 1024>>>(ada_gss, cond_BD);                           // 0
    ln_mod_kernel<<<NROWS, 256>>>(x, mh, ml, 2, 4);                              // 1
    split_kernel<<<NROWS * CH / 4096, 256>>>(context, ch_, cl_, NROWS * CH / 4); // 2

    Split3Args s3;
    s3.src[0] = Wq; s3.hi[0] = wqh; s3.lo[0] = wql;
    s3.src[1] = Wk; s3.hi[1] = wkh; s3.lo[1] = wkl;
    s3.src[2] = Wv; s3.hi[2] = wvh; s3.lo[2] = wvl;
    split3_kernel<<<dim3(CH * CH / 4096, 3), 256>>>(s3, CH * CH / 4);            // 3
    split_kernel<<<CH * CH / 4096, 256>>>(Wo, woh, wol, CH * CH / 4);            // 4

    QkvArgs qa;
    qa.ah[0] = mh;  qa.al[0] = ml;  qa.bh[0] = wqh; qa.bl[0] = wql;
    qa.yh[0] = qh;  qa.yl[0] = ql;
    qa.ah[1] = ch_; qa.al[1] = cl_; qa.bh[1] = wkh; qa.bl[1] = wkl;
    qa.yh[1] = kh;  qa.yl[1] = kl;
    qa.ah[2] = ch_; qa.al[2] = cl_; qa.bh[2] = wvh; qa.bl[2] = wvl;
    qa.yh[2] = vh;  qa.yl[2] = vl;
    gemm_qkv<<<dim3(8, 32, 3), 256, GEMM_SMEM>>>(qa);                            // 5

    split_kernel<<<FFNDIM * CH / 4096, 256>>>(W1, w1h, w1l, FFNDIM * CH / 4);    // 6
    split_kernel<<<FFNDIM * CH / 4096, 256>>>(W2, w2h, w2l, FFNDIM * CH / 4);    // 7

    attn_mma<<<dim3(NB * NH, SEQ / 128), 256, ATT_SMEM>>>(qh, ql, kh, kl, vh, vl,
                                                          attn_bias, aoh, aol);  // 8

    gemm_bf3<1><<<dim3(8, 32), 256, GEMM_SMEM>>>(aoh, aol, woh, wol, x1_p,
                                                 nullptr, nullptr,
                                                 NROWS, CH, CH,
                                                 bo, g_p + 0 * CH, x);           // 9

    ln_mod_kernel<<<NROWS, 256>>>(x1_p, mh, ml, 3, 5);                           // 10

    gemm_bf3<2><<<dim3(32, 32), 256, GEMM_SMEM>>>(mh, ml, w1h, w1l, nullptr,
                                                  hh, hl,
                                                  NROWS, FFNDIM, CH,
                                                  b1, nullptr, nullptr);         // 11

    gemm_bf3<3><<<dim3(8, 32), 256, GEMM_SMEM>>>(hh, hl, w2h, w2l, out,
                                                 nullptr, nullptr,
                                                 NROWS, CH, FFNDIM,
                                                 b2, g_p + 1 * CH, x1_p);        // 12
}

// round 10
// speedup vs baseline: 1.1229x; 1.1229x over previous
#include <cuda_runtime.h>
#include <cuda_bf16.h>
#include <cstdint>
#include <math.h>

// Problem constants
#define NB 4
#define SEQ 1024
#define CH 1024
#define NH 16
#define DH 64
#define NROWS (NB * SEQ)
#define FFNDIM (4 * CH)
#define ASCALE 0.03125f
#define LNEPS 1e-5f

typedef __nv_bfloat16 bf16;
typedef __nv_bfloat162 bf162;

// ---------------- scratch ----------------------------------------------------
__device__ float g_buf[NB * 6 * CH];
__device__ float x1_buf[(size_t)NROWS * CH];

__device__ bf16 wq_h[CH * CH], wq_l[CH * CH];
__device__ bf16 wk_h[CH * CH], wk_l[CH * CH];
__device__ bf16 wv_h[CH * CH], wv_l[CH * CH];
__device__ bf16 wo_h[CH * CH], wo_l[CH * CH];
__device__ bf16 w1_h[(size_t)FFNDIM * CH], w1_l[(size_t)FFNDIM * CH];
__device__ bf16 w2_h[(size_t)CH * FFNDIM], w2_l[(size_t)CH * FFNDIM];
__device__ bf16 ctx_h[(size_t)NROWS * CH], ctx_l[(size_t)NROWS * CH];
__device__ bf16 mod_h[(size_t)NROWS * CH], mod_l[(size_t)NROWS * CH];
__device__ bf16 ao_h[(size_t)NROWS * CH], ao_l[(size_t)NROWS * CH];
__device__ bf16 hb_h[(size_t)NROWS * FFNDIM], hb_l[(size_t)NROWS * FFNDIM];
__device__ bf16 q_h[(size_t)NROWS * CH], q_l[(size_t)NROWS * CH];
__device__ bf16 k_h[(size_t)NROWS * CH], k_l[(size_t)NROWS * CH];
__device__ bf16 v_h[(size_t)NROWS * CH], v_l[(size_t)NROWS * CH];

// ---------------- PTX helpers ------------------------------------------------
__device__ __forceinline__ uint32_t smem_u32(const void* p) {
    uint32_t a;
    asm("{ .reg .u64 t; cvta.to.shared.u64 t, %1; cvt.u32.u64 %0, t; }"
        : "=r"(a) : "l"(p));
    return a;
}
__device__ __forceinline__ void cp_async16(uint32_t sa, const void* ga) {
    asm volatile("cp.async.cg.shared.global [%0], [%1], 16;"
                 :: "r"(sa), "l"(ga) : "memory");
}
#define CP_COMMIT() asm volatile("cp.async.commit_group;" ::: "memory")
#define CP_WAIT(n)  asm volatile("cp.async.wait_group %0;" :: "n"(n) : "memory")

#define LDSM4(r0, r1, r2, r3, addr) \
    asm volatile("ldmatrix.sync.aligned.m8n8.x4.shared.b16 {%0,%1,%2,%3}, [%4];" \
                 : "=r"(r0), "=r"(r1), "=r"(r2), "=r"(r3) : "r"(addr))

#define LDSM4T(r0, r1, r2, r3, addr) \
    asm volatile("ldmatrix.sync.aligned.m8n8.x4.trans.shared.b16 {%0,%1,%2,%3}, [%4];" \
                 : "=r"(r0), "=r"(r1), "=r"(r2), "=r"(r3) : "r"(addr))

#define MMA_BF16(c, a, b) \
    asm volatile( \
        "mma.sync.aligned.m16n8k16.row.col.f32.bf16.bf16.f32 " \
        "{%0,%1,%2,%3}, {%4,%5,%6,%7}, {%8,%9}, {%0,%1,%2,%3};" \
        : "+f"((c)[0]), "+f"((c)[1]), "+f"((c)[2]), "+f"((c)[3]) \
        : "r"((a)[0]), "r"((a)[1]), "r"((a)[2]), "r"((a)[3]), \
          "r"((b)[0]), "r"((b)[1]))

#define MMA_BF16_2(c, a, b0, b1) \
    asm volatile( \
        "mma.sync.aligned.m16n8k16.row.col.f32.bf16.bf16.f32 " \
        "{%0,%1,%2,%3}, {%4,%5,%6,%7}, {%8,%9}, {%0,%1,%2,%3};" \
        : "+f"((c)[0]), "+f"((c)[1]), "+f"((c)[2]), "+f"((c)[3]) \
        : "r"((a)[0]), "r"((a)[1]), "r"((a)[2]), "r"((a)[3]), \
          "r"(b0), "r"(b1))

// GEMM tiles: [128 rows][32 bf16 = 64B], 4 groups of 16B
__device__ __forceinline__ uint32_t sw_off(int row, int g) {
    return (uint32_t)(row * 64 + (((g ^ (row >> 1)) & 3) << 4));
}
// Attention tiles: [rows][64 bf16 = 128B], 8 groups of 16B
__device__ __forceinline__ uint32_t sw128(int row, int g) {
    return (uint32_t)(row * 128 + (((g ^ row) & 7) << 4));
}

__device__ __forceinline__ void split_f(float x, bf16& h, bf16& l) {
    h = __float2bfloat16_rn(x);
    l = __float2bfloat16_rn(x - __bfloat162float(h));
}
__device__ __forceinline__ uint32_t pack_bf2(float a, float b) {
    bf162 t = __floats2bfloat162_rn(a, b);
    return *(uint32_t*)&t;
}

// ---------------- g = ada_gss + cond_BD -------------------------------------
__global__ void add_params_kernel(const float* __restrict__ ada,
                                  const float* __restrict__ cond) {
    int i = blockIdx.x * blockDim.x + threadIdx.x;
    if (i < NB * 6 * CH) g_buf[i] = ada[i % (6 * CH)] + cond[i];
}

// ---------------- fp32 -> (bf16 hi, bf16 lo) split (4x float4 / thread) -----
__device__ __forceinline__ void split_store(const float* __restrict__ src,
                                            bf16* __restrict__ hi,
                                            bf16* __restrict__ lo, int i) {
    float4 v = ((const float4*)src)[i];
    bf16 h0, h1, h2, h3, l0, l1, l2, l3;
    split_f(v.x, h0, l0); split_f(v.y, h1, l1);
    split_f(v.z, h2, l2); split_f(v.w, h3, l3);
    bf162* hp = (bf162*)(hi + (size_t)i * 4);
    bf162* lp = (bf162*)(lo + (size_t)i * 4);
    hp[0] = bf162(h0, h1); hp[1] = bf162(h2, h3);
    lp[0] = bf162(l0, l1); lp[1] = bf162(l2, l3);
}

__global__ void split_kernel(const float* __restrict__ src,
                             bf16* __restrict__ hi, bf16* __restrict__ lo,
                             int n4) {
    int i = blockIdx.x * 1024 + threadIdx.x;
    #pragma unroll
    for (int c = 0; c < 4; c++, i += 256)
        if (i < n4) split_store(src, hi, lo, i);
}

// four splits in one launch (blockIdx.y selects tensor)
struct Split4Args {
    const float* src[4];
    bf16* hi[4];
    bf16* lo[4];
};
__global__ void split4_kernel(Split4Args a, int n4) {
    int z = blockIdx.y;
    int i = blockIdx.x * 1024 + threadIdx.x;
    #pragma unroll
    for (int c = 0; c < 4; c++, i += 256)
        if (i < n4) split_store(a.src[z], a.hi[z], a.lo[z], i);
}

// ---------------- LayerNorm + AdaLN modulate -> hi/lo planes ----------------
__global__ void ln_mod_kernel(const float* __restrict__ X,
                              bf16* __restrict__ Oh, bf16* __restrict__ Ol,
                              int si, int hi) {
    int row = blockIdx.x;
    int b = row >> 10;
    int t = threadIdx.x;
    const float4* xr = (const float4*)(X + (size_t)row * CH);
    float4 v = xr[t];

    __shared__ float red[8];
    float s = v.x + v.y + v.z + v.w;
    #pragma unroll
    for (int o = 16; o; o >>= 1) s += __shfl_xor_sync(0xffffffffu, s, o);
    if ((t & 31) == 0) red[t >> 5] = s;
    __syncthreads();
    float tot = 0.f;
    #pragma unroll
    for (int w = 0; w < 8; w++) tot += red[w];
    float mean = tot * (1.0f / CH);

    float dx = v.x - mean, dy = v.y - mean, dz = v.z - mean, dw = v.w - mean;
    float s2 = dx * dx + dy * dy + dz * dz + dw * dw;
    #pragma unroll
    for (int o = 16; o; o >>= 1) s2 += __shfl_xor_sync(0xffffffffu, s2, o);
    __syncthreads();
    if ((t & 31) == 0) red[t >> 5] = s2;
    __syncthreads();
    float tot2 = 0.f;
    #pragma unroll
    for (int w = 0; w < 8; w++) tot2 += red[w];
    float rstd = rsqrtf(tot2 * (1.0f / CH) + LNEPS);

    const float* gb = g_buf + (size_t)b * 6 * CH;
    float4 sc = *(const float4*)(gb + si * CH + t * 4);
    float4 sh = *(const float4*)(gb + hi * CH + t * 4);
    float m0 = dx * rstd * (1.0f + sc.x) + sh.x;
    float m1 = dy * rstd * (1.0f + sc.y) + sh.y;
    float m2 = dz * rstd * (1.0f + sc.z) + sh.z;
    float m3 = dw * rstd * (1.0f + sc.w) + sh.w;

    bf16 h0, h1, h2, h3, l0, l1, l2, l3;
    split_f(m0, h0, l0); split_f(m1, h1, l1);
    split_f(m2, h2, l2); split_f(m3, h3, l3);
    size_t base = (size_t)row * CH + t * 4;
    bf162* hp = (bf162*)(Oh + base);
    bf162* lp = (bf162*)(Ol + base);
    hp[0] = bf162(h0, h1); hp[1] = bf162(h2, h3);
    lp[0] = bf162(l0, l1); lp[1] = bf162(l2, l3);
}

__device__ __forceinline__ float gelu_tanh(float u) {
    float z = 0.7978845608028654f * (u + 0.044715f * u * u * u);
    float e = __expf(-2.0f * z);
    return u / (1.0f + e);
}

// ---------------- 3xbf16 mma.sync GEMM core (R8-proven: 2 CTA/SM) -----------
#define BKB 32
#define GSTAGES 3
#define PLANE_BYTES 8192
#define STAGE_BYTES (4 * PLANE_BYTES)
#define GEMM_SMEM (GSTAGES * STAGE_BYTES)

// MODE 0: Yf = dot
// MODE 1/3: Yf = xres + (dot + bias[n]) * gam[b*6C + n]
// MODE 2: (Yh, Yl) = split(gelu(dot + bias[n]))
// MODE 4: (Yh, Yl) = split(dot)
template <int MODE>
__device__ __forceinline__ void gemm_core(
        const bf16* __restrict__ Ah, const bf16* __restrict__ Al,
        const bf16* __restrict__ Bh, const bf16* __restrict__ Bl,
        float* __restrict__ Yf, bf16* __restrict__ Yh, bf16* __restrict__ Yl,
        int N, int K,
        const float* __restrict__ bias, const float* __restrict__ gam,
        const float* __restrict__ xres,
        uint32_t smb, int bm, int bn) {
    int tid = threadIdx.x;
    int lane = tid & 31, wid = tid >> 5;
    int wm = wid >> 2;
    int wn = wid & 3;
    const int NC = K / BKB;

    auto issue = [&](int c, int st) {
        uint32_t s0 = smb + st * STAGE_BYTES;
        #pragma unroll
        for (int half = 0; half < 2; half++) {
            int i = half * 256 + tid;
            int row = i >> 2, g = i & 3;
            uint32_t so = sw_off(row, g);
            size_t aoff = (size_t)(bm + row) * K + c * BKB + g * 8;
            size_t boff = (size_t)(bn + row) * K + c * BKB + g * 8;
            cp_async16(s0 + so, Ah + aoff);
            cp_async16(s0 + PLANE_BYTES + so, Al + aoff);
            cp_async16(s0 + 2 * PLANE_BYTES + so, Bh + boff);
            cp_async16(s0 + 3 * PLANE_BYTES + so, Bl + boff);
        }
        CP_COMMIT();
    };

    issue(0, 0);
    issue(1, 1);

    float c[16][4];
    #pragma unroll
    for (int i = 0; i < 16; i++)
        #pragma unroll
        for (int j = 0; j < 4; j++) c[i][j] = 0.f;

    int a_row_base = wm * 64 + ((lane >> 3) & 1) * 8 + (lane & 7);
    int a_g_base = (lane >> 4);
    int b_row_base = wn * 32 + ((lane >> 4) & 1) * 8 + (lane & 7);
    int b_g_base = ((lane >> 3) & 1);

    int sidx = 0, pidx = 2;
    for (int kt = 0; kt < NC; kt++) {
        if (kt + 1 < NC) { CP_WAIT(1); } else { CP_WAIT(0); }
        __syncthreads();
        if (kt + 2 < NC) issue(kt + 2, pidx);

        uint32_t sAh = smb + sidx * STAGE_BYTES;
        uint32_t sAl = sAh + PLANE_BYTES;
        uint32_t sBh = sAh + 2 * PLANE_BYTES;
        uint32_t sBl = sAh + 3 * PLANE_BYTES;

        #pragma unroll
        for (int ks = 0; ks < 2; ks++) {
            int ag = ks * 2 + a_g_base;
            int bg = ks * 2 + b_g_base;
            uint32_t bh[4][2], bl[4][2];
            #pragma unroll
            for (int tp = 0; tp < 2; tp++) {
                uint32_t so = sw_off(b_row_base + tp * 16, bg);
                uint32_t r0, r1, r2, r3;
                LDSM4(r0, r1, r2, r3, sBh + so);
                bh[tp * 2][0] = r0;     bh[tp * 2][1] = r1;
                bh[tp * 2 + 1][0] = r2; bh[tp * 2 + 1][1] = r3;
                LDSM4(r0, r1, r2, r3, sBl + so);
                bl[tp * 2][0] = r0;     bl[tp * 2][1] = r1;
                bl[tp * 2 + 1][0] = r2; bl[tp * 2 + 1][1] = r3;
            }
            #pragma unroll
            for (int tm = 0; tm < 4; tm++) {
                uint32_t ah[4], al[4];
                uint32_t so = sw_off(a_row_base + tm * 16, ag);
                LDSM4(ah[0], ah[1], ah[2], ah[3], sAh + so);
                LDSM4(al[0], al[1], al[2], al[3], sAl + so);
                #pragma unroll
                for (int tn = 0; tn < 4; tn++) {
                    MMA_BF16(c[tm * 4 + tn], ah, bh[tn]);
                    MMA_BF16(c[tm * 4 + tn], ah, bl[tn]);
                    MMA_BF16(c[tm * 4 + tn], al, bh[tn]);
                }
            }
        }
        sidx = (sidx + 1 == GSTAGES) ? 0 : sidx + 1;
        pidx = (pidx + 1 == GSTAGES) ? 0 : pidx + 1;
    }

    #pragma unroll
    for (int tm = 0; tm < 4; tm++) {
        #pragma unroll
        for (int half = 0; half < 2; half++) {
            int row = bm + wm * 64 + tm * 16 + (lane >> 2) + half * 8;
            size_t rbase = (size_t)row * N;
            int bb = row >> 10;
            #pragma unroll
            for (int tn = 0; tn < 4; tn++) {
                int col = bn + wn * 32 + tn * 8 + (lane & 3) * 2;
                float d0 = c[tm * 4 + tn][half * 2 + 0];
                float d1 = c[tm * 4 + tn][half * 2 + 1];
                if (MODE == 0) {
                    *(float2*)(Yf + rbase + col) = make_float2(d0, d1);
                } else if (MODE == 4) {
                    bf16 h0, h1, l0, l1;
                    split_f(d0, h0, l0);
                    split_f(d1, h1, l1);
                    *(bf162*)(Yh + rbase + col) = bf162(h0, h1);
                    *(bf162*)(Yl + rbase + col) = bf162(l0, l1);
                } else if (MODE == 2) {
                    float2 bi = *(const float2*)(bias + col);
                    d0 = gelu_tanh(d0 + bi.x);
                    d1 = gelu_tanh(d1 + bi.y);
                    bf16 h0, h1, l0, l1;
                    split_f(d0, h0, l0);
                    split_f(d1, h1, l1);
                    *(bf162*)(Yh + rbase + col) = bf162(h0, h1);
                    *(bf162*)(Yl + rbase + col) = bf162(l0, l1);
                } else {
                    float2 bi = *(const float2*)(bias + col);
                    d0 += bi.x; d1 += bi.y;
                    float2 gv = *(const float2*)(gam + (size_t)bb * 6 * CH + col);
                    float2 xr = *(const float2*)(xres + rbase + col);
                    *(float2*)(Yf + rbase + col) =
                        make_float2(xr.x + d0 * gv.x, xr.y + d1 * gv.y);
                }
            }
        }
    }
}

template <int MODE>
__global__ void __launch_bounds__(256, 2)
gemm_bf3(const bf16* __restrict__ Ah, const bf16* __restrict__ Al,
         const bf16* __restrict__ Bh, const bf16* __restrict__ Bl,
         float* __restrict__ Yf, bf16* __restrict__ Yh, bf16* __restrict__ Yl,
         int M, int N, int K,
         const float* __restrict__ bias, const float* __restrict__ gam,
         const float* __restrict__ xres) {
    extern __shared__ char smraw[];
    gemm_core<MODE>(Ah, Al, Bh, Bl, Yf, Yh, Yl, N, K, bias, gam, xres,
                    smem_u32(smraw), blockIdx.y * 128, blockIdx.x * 128);
}

// merged Q/K/V projection: blockIdx.z selects the (A, B, Y) triple
struct QkvArgs {
    const bf16 *ah[3], *al[3], *bh[3], *bl[3];
    bf16 *yh[3], *yl[3];
};
__global__ void __launch_bounds__(256, 2)
gemm_qkv(QkvArgs a) {
    extern __shared__ char smraw[];
    int z = blockIdx.z;
    gemm_core<4>(a.ah[z], a.al[z], a.bh[z], a.bl[z],
                 nullptr, a.yh[z], a.yl[z], CH, CH,
                 nullptr, nullptr, nullptr,
                 smem_u32(smraw), blockIdx.y * 128, blockIdx.x * 128);
}

// ---------------- FA2-style attention (R8 shape: 64 q-rows / 4 warps) -------
// smem: Q hi/lo [64][64] (16KB) + 2 stages x (Kh,Kl,Vh,Vl [64][64]) (64KB)
// bias loads register-double-buffered: tile kt+1's bias LDGs issue right
// after tile kt's bias is consumed, hiding global latency behind softmax+PV.
#define ATT_SMEM (16384 + 2 * 32768)

__global__ void __launch_bounds__(128)
attn_mma(const bf16* __restrict__ Qh, const bf16* __restrict__ Ql,
         const bf16* __restrict__ Kh, const bf16* __restrict__ Kl,
         const bf16* __restrict__ Vh, const bf16* __restrict__ Vl,
         const float* __restrict__ bias,
         bf16* __restrict__ Oh, bf16* __restrict__ Ol) {
    extern __shared__ char smraw[];
    uint32_t smb = smem_u32(smraw);
    int tid = threadIdx.x;
    int lane = tid & 31, w = tid >> 5;
    int bh = blockIdx.x;
    int b = bh >> 4, h = bh & 15;
    int q0 = blockIdx.y * 64;

    {
        const bf16* qp[2] = {Qh, Ql};
        #pragma unroll
        for (int it = 0; it < 8; it++) {
            int pl = it >> 2;
            int row = (it & 3) * 16 + (tid >> 3);
            int g = tid & 7;
            cp_async16(smb + pl * 8192 + sw128(row, g),
                       qp[pl] + (size_t)(b * SEQ + q0 + row) * CH + h * DH + g * 8);
        }
    }
    auto issue_tile = [&](int kt) {
        uint32_t st = smb + 16384 + (kt & 1) * 32768;
        const bf16* pp[4] = {Kh, Kl, Vh, Vl};
        #pragma unroll
        for (int it = 0; it < 16; it++) {
            int pl = it >> 2;
            int row = (it & 3) * 16 + (tid >> 3);
            int g = tid & 7;
            cp_async16(st + pl * 8192 + sw128(row, g),
                       pp[pl] + (size_t)(b * SEQ + kt * 64 + row) * CH + h * DH + g * 8);
        }
    };
    issue_tile(0);
    CP_COMMIT();

    const float* bp0 = bias +
        ((size_t)(b * NH + h) * SEQ + q0 + w * 16 + (lane >> 2)) * SEQ + (lane & 3) * 2;

    // preload bias for tile 0 into registers
    float2 bufA[8], bufB[8];
    #pragma unroll
    for (int n = 0; n < 8; n++) {
        bufA[n] = *(const float2*)(bp0 + n * 8);
        bufB[n] = *(const float2*)(bp0 + (size_t)8 * SEQ + n * 8);
    }

    CP_WAIT(0);
    __syncthreads();

    uint32_t qhf[4][4], qlf[4][4];
    {
        int qrow = w * 16 + (lane & 15);
        #pragma unroll
        for (int ks = 0; ks < 4; ks++) {
            uint32_t so = sw128(qrow, ks * 2 + (lane >> 4));
            LDSM4(qhf[ks][0], qhf[ks][1], qhf[ks][2], qhf[ks][3], smb + so);
            LDSM4(qlf[ks][0], qlf[ks][1], qlf[ks][2], qlf[ks][3], smb + 8192 + so);
        }
    }

    float o[8][4];
    #pragma unroll
    for (int n = 0; n < 8; n++)
        #pragma unroll
        for (int j = 0; j < 4; j++) o[n][j] = 0.f;
    float miA = -1e30f, miB = -1e30f, liA = 0.f, liB = 0.f;

    for (int kt = 0; kt < 16; kt++) {
        if (kt + 1 < 16) { issue_tile(kt + 1); CP_COMMIT(); }

        uint32_t sKh = smb + 16384 + (kt & 1) * 32768;
        uint32_t sKl = sKh + 8192;
        uint32_t sVh = sKh + 16384;
        uint32_t sVl = sKh + 24576;

        float s[8][4];
        #pragma unroll
        for (int n = 0; n < 8; n++)
            #pragma unroll
            for (int j = 0; j < 4; j++) s[n][j] = 0.f;

        int krow_base = ((lane >> 4) & 1) * 8 + (lane & 7);
        int kg_base = (lane >> 3) & 1;
        #pragma unroll
        for (int ks = 0; ks < 4; ks++) {
            int kg = ks * 2 + kg_base;
            #pragma unroll
            for (int np = 0; np < 4; np++) {
                uint32_t so = sw128(np * 16 + krow_base, kg);
                uint32_t h0, h1, h2, h3, l0, l1, l2, l3;
                LDSM4(h0, h1, h2, h3, sKh + so);
                LDSM4(l0, l1, l2, l3, sKl + so);
                MMA_BF16_2(s[np * 2], qhf[ks], h0, h1);
                MMA_BF16_2(s[np * 2], qlf[ks], h0, h1);
                MMA_BF16_2(s[np * 2], qhf[ks], l0, l1);
                MMA_BF16_2(s[np * 2 + 1], qhf[ks], h2, h3);
                MMA_BF16_2(s[np * 2 + 1], qlf[ks], h2, h3);
                MMA_BF16_2(s[np * 2 + 1], qhf[ks], l2, l3);
            }
        }

        // consume preloaded bias for this tile
        #pragma unroll
        for (int n = 0; n < 8; n++) {
            s[n][0] = fmaf(s[n][0], ASCALE, bufA[n].x);
            s[n][1] = fmaf(s[n][1], ASCALE, bufA[n].y);
            s[n][2] = fmaf(s[n][2], ASCALE, bufB[n].x);
            s[n][3] = fmaf(s[n][3], ASCALE, bufB[n].y);
        }
        // immediately issue bias loads for the next tile (latency hidden by
        // the softmax + PV + next-tile QK work below)
        if (kt + 1 < 16) {
            const float* bp = bp0 + (kt + 1) * 64;
            #pragma unroll
            for (int n = 0; n < 8; n++) {
                bufA[n] = *(const float2*)(bp + n * 8);
                bufB[n] = *(const float2*)(bp + (size_t)8 * SEQ + n * 8);
            }
        }

        float mA = -1e30f, mB = -1e30f;
        #pragma unroll
        for (int n = 0; n < 8; n++) {
            mA = fmaxf(mA, fmaxf(s[n][0], s[n][1]));
            mB = fmaxf(mB, fmaxf(s[n][2], s[n][3]));
        }
        mA = fmaxf(mA, __shfl_xor_sync(0xffffffffu, mA, 1));
        mA = fmaxf(mA, __shfl_xor_sync(0xffffffffu, mA, 2));
        mB = fmaxf(mB, __shfl_xor_sync(0xffffffffu, mB, 1));
        mB = fmaxf(mB, __shfl_xor_sync(0xffffffffu, mB, 2));
        float mnA = fmaxf(miA, mA), mnB = fmaxf(miB, mB);
        float corrA = __expf(miA - mnA), corrB = __expf(miB - mnB);
        miA = mnA; miB = mnB;
        float rsA = 0.f, rsB = 0.f;
        #pragma unroll
        for (int n = 0; n < 8; n++) {
            s[n][0] = __expf(s[n][0] - mnA);
            s[n][1] = __expf(s[n][1] - mnA);
            s[n][2] = __expf(s[n][2] - mnB);
            s[n][3] = __expf(s[n][3] - mnB);
            rsA += s[n][0] + s[n][1];
            rsB += s[n][2] + s[n][3];
        }
        rsA += __shfl_xor_sync(0xffffffffu, rsA, 1);
        rsA += __shfl_xor_sync(0xffffffffu, rsA, 2);
        rsB += __shfl_xor_sync(0xffffffffu, rsB, 1);
        rsB += __shfl_xor_sync(0xffffffffu, rsB, 2);
        liA = liA * corrA + rsA;
        liB = liB * corrB + rsB;
        #pragma unroll
        for (int n = 0; n < 8; n++) {
            o[n][0] *= corrA; o[n][1] *= corrA;
            o[n][2] *= corrB; o[n][3] *= corrB;
        }

        int vrow_base = ((lane >> 3) & 1) * 8 + (lane & 7);
        int vg_base = (lane >> 4) & 1;
        #pragma unroll
        for (int kk = 0; kk < 4; kk++) {
            uint32_t pah[4], pal[4];
            #pragma unroll
            for (int q = 0; q < 2; q++) {
                int nf = kk * 2 + q;
                float p0 = s[nf][0], p1 = s[nf][1], p2 = s[nf][2], p3 = s[nf][3];
                float h0 = __bfloat162float(__float2bfloat16_rn(p0));
                float h1 = __bfloat162float(__float2bfloat16_rn(p1));
                float h2 = __bfloat162float(__float2bfloat16_rn(p2));
                float h3 = __bfloat162float(__float2bfloat16_rn(p3));
                pah[q * 2 + 0] = pack_bf2(h0, h1);
                pah[q * 2 + 1] = pack_bf2(h2, h3);
                pal[q * 2 + 0] = pack_bf2(p0 - h0, p1 - h1);
                pal[q * 2 + 1] = pack_bf2(p2 - h2, p3 - h3);
            }
            #pragma unroll
            for (int dp = 0; dp < 4; dp++) {
                uint32_t so = sw128(kk * 16 + vrow_base, dp * 2 + vg_base);
                uint32_t r0, r1, r2, r3;
                LDSM4T(r0, r1, r2, r3, sVh + so);
                MMA_BF16_2(o[dp * 2], pah, r0, r1);
                MMA_BF16_2(o[dp * 2], pal, r0, r1);
                MMA_BF16_2(o[dp * 2 + 1], pah, r2, r3);
                MMA_BF16_2(o[dp * 2 + 1], pal, r2, r3);
                LDSM4T(r0, r1, r2, r3, sVl + so);
                MMA_BF16_2(o[dp * 2], pah, r0, r1);
                MMA_BF16_2(o[dp * 2 + 1], pah, r2, r3);
            }
        }

        if (kt + 1 < 16) { CP_WAIT(0); __syncthreads(); }
    }

    float invA = 1.0f / liA, invB = 1.0f / liB;
    size_t rowA = (size_t)(b * SEQ + q0 + w * 16 + (lane >> 2));
    #pragma unroll
    for (int n = 0; n < 8; n++) {
        int col = h * DH + n * 8 + (lane & 3) * 2;
        float f0 = o[n][0] * invA, f1 = o[n][1] * invA;
        float f2 = o[n][2] * invB, f3 = o[n][3] * invB;
        bf16 h0, h1, h2, h3, l0, l1, l2, l3;
        split_f(f0, h0, l0); split_f(f1, h1, l1);
        split_f(f2, h2, l2); split_f(f3, h3, l3);
        *(bf162*)(Oh + rowA * CH + col) = bf162(h0, h1);
        *(bf162*)(Ol + rowA * CH + col) = bf162(l0, l1);
        *(bf162*)(Oh + (rowA + 8) * CH + col) = bf162(h2, h3);
        *(bf162*)(Ol + (rowA + 8) * CH + col) = bf162(l2, l3);
    }
}

// ---------------- launch ------------------------------------------------------
extern "C" void kernel_launch(void* const* d_in, const int* in_sizes, int n_in,
                              void* d_out, int out_size) {
    const float* x         = (const float*)d_in[0];
    const float* context   = (const float*)d_in[1];
    const float* cond_BD   = (const float*)d_in[2];
    const float* attn_bias = (const float*)d_in[3];
    const float* ada_gss   = (const float*)d_in[4];
    const float* Wq        = (const float*)d_in[5];
    const float* Wk        = (const float*)d_in[6];
    const float* Wv        = (const float*)d_in[7];
    const float* Wo        = (const float*)d_in[8];
    const float* bo        = (const float*)d_in[9];
    const float* W1        = (const float*)d_in[10];
    const float* b1        = (const float*)d_in[11];
    const float* W2        = (const float*)d_in[12];
    const float* b2        = (const float*)d_in[13];
    float* out = (float*)d_out;

    float *g_p, *x1_p;
    cudaGetSymbolAddress((void**)&g_p, g_buf);
    cudaGetSymbolAddress((void**)&x1_p, x1_buf);

    bf16 *wqh, *wql, *wkh, *wkl, *wvh, *wvl, *woh, *wol;
    bf16 *w1h, *w1l, *w2h, *w2l, *ch_, *cl_, *mh, *ml, *aoh, *aol, *hh, *hl;
    bf16 *qh, *ql, *kh, *kl, *vh, *vl;
    cudaGetSymbolAddress((void**)&wqh, wq_h); cudaGetSymbolAddress((void**)&wql, wq_l);
    cudaGetSymbolAddress((void**)&wkh, wk_h); cudaGetSymbolAddress((void**)&wkl, wk_l);
    cudaGetSymbolAddress((void**)&wvh, wv_h); cudaGetSymbolAddress((void**)&wvl, wv_l);
    cudaGetSymbolAddress((void**)&woh, wo_h); cudaGetSymbolAddress((void**)&wol, wo_l);
    cudaGetSymbolAddress((void**)&w1h, w1_h); cudaGetSymbolAddress((void**)&w1l, w1_l);
    cudaGetSymbolAddress((void**)&w2h, w2_h); cudaGetSymbolAddress((void**)&w2l, w2_l);
    cudaGetSymbolAddress((void**)&ch_, ctx_h); cudaGetSymbolAddress((void**)&cl_, ctx_l);
    cudaGetSymbolAddress((void**)&mh, mod_h);  cudaGetSymbolAddress((void**)&ml, mod_l);
    cudaGetSymbolAddress((void**)&aoh, ao_h);  cudaGetSymbolAddress((void**)&aol, ao_l);
    cudaGetSymbolAddress((void**)&hh, hb_h);   cudaGetSymbolAddress((void**)&hl, hb_l);
    cudaGetSymbolAddress((void**)&qh, q_h);    cudaGetSymbolAddress((void**)&ql, q_l);
    cudaGetSymbolAddress((void**)&kh, k_h);    cudaGetSymbolAddress((void**)&kl, k_l);
    cudaGetSymbolAddress((void**)&vh, v_h);    cudaGetSymbolAddress((void**)&vl, v_l);

    cudaFuncSetAttribute(attn_mma,
                         cudaFuncAttributeMaxDynamicSharedMemorySize, ATT_SMEM);
    cudaFuncSetAttribute(gemm_qkv,
                         cudaFuncAttributeMaxDynamicSharedMemorySize, GEMM_SMEM);
    cudaFuncSetAttribute(gemm_bf3<1>,
                         cudaFuncAttributeMaxDynamicSharedMemorySize, GEMM_SMEM);
    cudaFuncSetAttribute(gemm_bf3<2>,
                         cudaFuncAttributeMaxDynamicSharedMemorySize, GEMM_SMEM);
    cudaFuncSetAttribute(gemm_bf3<3>,
                         cudaFuncAttributeMaxDynamicSharedMemorySize, GEMM_SMEM);

    add_params_kernel<<<24, 1024>>>(ada_gss, cond_BD);                           // 0
    ln_mod_kernel<<<NROWS, 256>>>(x, mh, ml, 2, 4);                              // 1
    split_kernel<<<NROWS * CH / 4096, 256>>>(context, ch_, cl_, NROWS * CH / 4); // 2

    Split4Args s4;
    s4.src[0] = Wq; s4.hi[0] = wqh; s4.lo[0] = wql;
    s4.src[1] = Wk; s4.hi[1] = wkh; s4.lo[1] = wkl;
    s4.src[2] = Wv; s4.hi[2] = wvh; s4.lo[2] = wvl;
    s4.src[3] = Wo; s4.hi[3] = woh; s4.lo[3] = wol;
    split4_kernel<<<dim3(CH * CH / 4096, 4), 256>>>(s4, CH * CH / 4);            // 3
    split_kernel<<<FFNDIM * CH / 4096, 256>>>(W1, w1h, w1l, FFNDIM * CH / 4);    // 4

    QkvArgs qa;
    qa.ah[0] = mh;  qa.al[0] = ml;  qa.bh[0] = wqh; qa.bl[0] = wql;
    qa.yh[0] = qh;  qa.yl[0] = ql;
    qa.ah[1] = ch_; qa.al[1] = cl_; qa.bh[1] = wkh; qa.bl[1] = wkl;
    qa.yh[1] = kh;  qa.yl[1] = kl;
    qa.ah[2] = ch_; qa.al[2] = cl_; qa.bh[2] = wvh; qa.bl[2] = wvl;
    qa.yh[2] = vh;  qa.yl[2] = vl;
    gemm_qkv<<<dim3(8, 32, 3), 256, GEMM_SMEM>>>(qa);                            // 5

    split_kernel<<<FFNDIM * CH / 4096, 256>>>(W2, w2h, w2l, FFNDIM * CH / 4);    // 6

    attn_mma<<<dim3(NB * NH, SEQ / 64), 128, ATT_SMEM>>>(qh, ql, kh, kl, vh, vl,
                                                         attn_bias, aoh, aol);   // 7

    gemm_bf3<1><<<dim3(8, 32), 256, GEMM_SMEM>>>(aoh, aol, woh, wol, x1_p,
                                                 nullptr, nullptr,
                                                 NROWS, CH, CH,
                                                 bo, g_p + 0 * CH, x);           // 8

    ln_mod_kernel<<<NROWS, 256>>>(x1_p, mh, ml, 3, 5);                           // 9

    gemm_bf3<2><<<dim3(32, 32), 256, GEMM_SMEM>>>(mh, ml, w1h, w1l, nullptr,
                                                  hh, hl,
                                                  NROWS, FFNDIM, CH,
                                                  b1, nullptr, nullptr);         // 10

    gemm_bf3<3><<<dim3(8, 32), 256, GEMM_SMEM>>>(hh, hl, w2h, w2l, out,
                                                 nullptr, nullptr,
                                                 NROWS, CH, FFNDIM,
                                                 b2, g_p + 1 * CH, x1_p);        // 11
}

// round 11
// speedup vs baseline: 1.1389x; 1.0143x over previous
#include <cuda_runtime.h>
#include <cuda_bf16.h>
#include <cstdint>
#include <math.h>

// Problem constants
#define NB 4
#define SEQ 1024
#define CH 1024
#define NH 16
#define DH 64
#define NROWS (NB * SEQ)
#define FFNDIM (4 * CH)
#define ASCALE 0.03125f
#define LNEPS 1e-5f

typedef __nv_bfloat16 bf16;
typedef __nv_bfloat162 bf162;

// ---------------- scratch ----------------------------------------------------
__device__ float g_buf[NB * 6 * CH];
__device__ float x1_buf[(size_t)NROWS * CH];

__device__ bf16 wq_h[CH * CH], wq_l[CH * CH];
__device__ bf16 wk_h[CH * CH], wk_l[CH * CH];
__device__ bf16 wv_h[CH * CH], wv_l[CH * CH];
__device__ bf16 wo_h[CH * CH], wo_l[CH * CH];
__device__ bf16 w1_h[(size_t)FFNDIM * CH], w1_l[(size_t)FFNDIM * CH];
__device__ bf16 w2_h[(size_t)CH * FFNDIM], w2_l[(size_t)CH * FFNDIM];
__device__ bf16 ctx_h[(size_t)NROWS * CH], ctx_l[(size_t)NROWS * CH];
__device__ bf16 mod_h[(size_t)NROWS * CH], mod_l[(size_t)NROWS * CH];
__device__ bf16 ao_h[(size_t)NROWS * CH], ao_l[(size_t)NROWS * CH];
__device__ bf16 hb_h[(size_t)NROWS * FFNDIM], hb_l[(size_t)NROWS * FFNDIM];
__device__ bf16 q_h[(size_t)NROWS * CH], q_l[(size_t)NROWS * CH];
__device__ bf16 k_h[(size_t)NROWS * CH], k_l[(size_t)NROWS * CH];
__device__ bf16 v_h[(size_t)NROWS * CH], v_l[(size_t)NROWS * CH];

// ---------------- PTX helpers ------------------------------------------------
__device__ __forceinline__ uint32_t smem_u32(const void* p) {
    uint32_t a;
    asm("{ .reg .u64 t; cvta.to.shared.u64 t, %1; cvt.u32.u64 %0, t; }"
        : "=r"(a) : "l"(p));
    return a;
}
__device__ __forceinline__ void cp_async16(uint32_t sa, const void* ga) {
    asm volatile("cp.async.cg.shared.global [%0], [%1], 16;"
                 :: "r"(sa), "l"(ga) : "memory");
}
#define CP_COMMIT() asm volatile("cp.async.commit_group;" ::: "memory")
#define CP_WAIT(n)  asm volatile("cp.async.wait_group %0;" :: "n"(n) : "memory")

#define LDSM4(r0, r1, r2, r3, addr) \
    asm volatile("ldmatrix.sync.aligned.m8n8.x4.shared.b16 {%0,%1,%2,%3}, [%4];" \
                 : "=r"(r0), "=r"(r1), "=r"(r2), "=r"(r3) : "r"(addr))

#define LDSM4T(r0, r1, r2, r3, addr) \
    asm volatile("ldmatrix.sync.aligned.m8n8.x4.trans.shared.b16 {%0,%1,%2,%3}, [%4];" \
                 : "=r"(r0), "=r"(r1), "=r"(r2), "=r"(r3) : "r"(addr))

#define MMA_BF16(c, a, b) \
    asm volatile( \
        "mma.sync.aligned.m16n8k16.row.col.f32.bf16.bf16.f32 " \
        "{%0,%1,%2,%3}, {%4,%5,%6,%7}, {%8,%9}, {%0,%1,%2,%3};" \
        : "+f"((c)[0]), "+f"((c)[1]), "+f"((c)[2]), "+f"((c)[3]) \
        : "r"((a)[0]), "r"((a)[1]), "r"((a)[2]), "r"((a)[3]), \
          "r"((b)[0]), "r"((b)[1]))

#define MMA_BF16_2(c, a, b0, b1) \
    asm volatile( \
        "mma.sync.aligned.m16n8k16.row.col.f32.bf16.bf16.f32 " \
        "{%0,%1,%2,%3}, {%4,%5,%6,%7}, {%8,%9}, {%0,%1,%2,%3};" \
        : "+f"((c)[0]), "+f"((c)[1]), "+f"((c)[2]), "+f"((c)[3]) \
        : "r"((a)[0]), "r"((a)[1]), "r"((a)[2]), "r"((a)[3]), \
          "r"(b0), "r"(b1))

// GEMM tiles: [128 rows][32 bf16 = 64B], 4 groups of 16B
__device__ __forceinline__ uint32_t sw_off(int row, int g) {
    return (uint32_t)(row * 64 + (((g ^ (row >> 1)) & 3) << 4));
}
// Attention tiles: [rows][64 bf16 = 128B], 8 groups of 16B
__device__ __forceinline__ uint32_t sw128(int row, int g) {
    return (uint32_t)(row * 128 + (((g ^ row) & 7) << 4));
}

__device__ __forceinline__ void split_f(float x, bf16& h, bf16& l) {
    h = __float2bfloat16_rn(x);
    l = __float2bfloat16_rn(x - __bfloat162float(h));
}
__device__ __forceinline__ uint32_t pack_bf2(float a, float b) {
    bf162 t = __floats2bfloat162_rn(a, b);
    return *(uint32_t*)&t;
}

// ---------------- g = ada_gss + cond_BD -------------------------------------
__global__ void add_params_kernel(const float* __restrict__ ada,
                                  const float* __restrict__ cond) {
    int i = blockIdx.x * blockDim.x + threadIdx.x;
    if (i < NB * 6 * CH) g_buf[i] = ada[i % (6 * CH)] + cond[i];
}

// ---------------- fp32 -> (bf16 hi, bf16 lo) split (4x float4 / thread) -----
__device__ __forceinline__ void split_store(const float* __restrict__ src,
                                            bf16* __restrict__ hi,
                                            bf16* __restrict__ lo, int i) {
    float4 v = ((const float4*)src)[i];
    bf16 h0, h1, h2, h3, l0, l1, l2, l3;
    split_f(v.x, h0, l0); split_f(v.y, h1, l1);
    split_f(v.z, h2, l2); split_f(v.w, h3, l3);
    bf162* hp = (bf162*)(hi + (size_t)i * 4);
    bf162* lp = (bf162*)(lo + (size_t)i * 4);
    hp[0] = bf162(h0, h1); hp[1] = bf162(h2, h3);
    lp[0] = bf162(l0, l1); lp[1] = bf162(l2, l3);
}

// seven splits in one launch (blockIdx.y selects tensor; ragged sizes)
struct Split7Args {
    const float* src[7];
    bf16* hi[7];
    bf16* lo[7];
    int n4[7];          // size in float4 units
};
__global__ void split7_kernel(Split7Args a) {
    int z = blockIdx.y;
    int n4 = a.n4[z];
    int i = blockIdx.x * 1024 + threadIdx.x;
    if (i >= n4) return;
    const float* src = a.src[z];
    bf16* hi = a.hi[z];
    bf16* lo = a.lo[z];
    #pragma unroll
    for (int c = 0; c < 4; c++, i += 256)
        if (i < n4) split_store(src, hi, lo, i);
}

// ---------------- LayerNorm + AdaLN modulate -> hi/lo planes ----------------
__global__ void ln_mod_kernel(const float* __restrict__ X,
                              bf16* __restrict__ Oh, bf16* __restrict__ Ol,
                              int si, int hi) {
    int row = blockIdx.x;
    int b = row >> 10;
    int t = threadIdx.x;
    const float4* xr = (const float4*)(X + (size_t)row * CH);
    float4 v = xr[t];

    __shared__ float red[8];
    float s = v.x + v.y + v.z + v.w;
    #pragma unroll
    for (int o = 16; o; o >>= 1) s += __shfl_xor_sync(0xffffffffu, s, o);
    if ((t & 31) == 0) red[t >> 5] = s;
    __syncthreads();
    float tot = 0.f;
    #pragma unroll
    for (int w = 0; w < 8; w++) tot += red[w];
    float mean = tot * (1.0f / CH);

    float dx = v.x - mean, dy = v.y - mean, dz = v.z - mean, dw = v.w - mean;
    float s2 = dx * dx + dy * dy + dz * dz + dw * dw;
    #pragma unroll
    for (int o = 16; o; o >>= 1) s2 += __shfl_xor_sync(0xffffffffu, s2, o);
    __syncthreads();
    if ((t & 31) == 0) red[t >> 5] = s2;
    __syncthreads();
    float tot2 = 0.f;
    #pragma unroll
    for (int w = 0; w < 8; w++) tot2 += red[w];
    float rstd = rsqrtf(tot2 * (1.0f / CH) + LNEPS);

    const float* gb = g_buf + (size_t)b * 6 * CH;
    float4 sc = *(const float4*)(gb + si * CH + t * 4);
    float4 sh = *(const float4*)(gb + hi * CH + t * 4);
    float m0 = dx * rstd * (1.0f + sc.x) + sh.x;
    float m1 = dy * rstd * (1.0f + sc.y) + sh.y;
    float m2 = dz * rstd * (1.0f + sc.z) + sh.z;
    float m3 = dw * rstd * (1.0f + sc.w) + sh.w;

    bf16 h0, h1, h2, h3, l0, l1, l2, l3;
    split_f(m0, h0, l0); split_f(m1, h1, l1);
    split_f(m2, h2, l2); split_f(m3, h3, l3);
    size_t base = (size_t)row * CH + t * 4;
    bf162* hp = (bf162*)(Oh + base);
    bf162* lp = (bf162*)(Ol + base);
    hp[0] = bf162(h0, h1); hp[1] = bf162(h2, h3);
    lp[0] = bf162(l0, l1); lp[1] = bf162(l2, l3);
}

__device__ __forceinline__ float gelu_tanh(float u) {
    float z = 0.7978845608028654f * (u + 0.044715f * u * u * u);
    float e = __expf(-2.0f * z);
    return u / (1.0f + e);
}

// ---------------- 3xbf16 mma.sync GEMM core (R8-proven: 2 CTA/SM) -----------
#define BKB 32
#define GSTAGES 3
#define PLANE_BYTES 8192
#define STAGE_BYTES (4 * PLANE_BYTES)
#define GEMM_SMEM (GSTAGES * STAGE_BYTES)

// MODE 0: Yf = dot
// MODE 1/3: Yf = xres + (dot + bias[n]) * gam[b*6C + n]
// MODE 2: (Yh, Yl) = split(gelu(dot + bias[n]))
// MODE 4: (Yh, Yl) = split(dot)
template <int MODE>
__device__ __forceinline__ void gemm_core(
        const bf16* __restrict__ Ah, const bf16* __restrict__ Al,
        const bf16* __restrict__ Bh, const bf16* __restrict__ Bl,
        float* __restrict__ Yf, bf16* __restrict__ Yh, bf16* __restrict__ Yl,
        int N, int K,
        const float* __restrict__ bias, const float* __restrict__ gam,
        const float* __restrict__ xres,
        uint32_t smb, int bm, int bn) {
    int tid = threadIdx.x;
    int lane = tid & 31, wid = tid >> 5;
    int wm = wid >> 2;
    int wn = wid & 3;
    const int NC = K / BKB;

    auto issue = [&](int c, int st) {
        uint32_t s0 = smb + st * STAGE_BYTES;
        #pragma unroll
        for (int half = 0; half < 2; half++) {
            int i = half * 256 + tid;
            int row = i >> 2, g = i & 3;
            uint32_t so = sw_off(row, g);
            size_t aoff = (size_t)(bm + row) * K + c * BKB + g * 8;
            size_t boff = (size_t)(bn + row) * K + c * BKB + g * 8;
            cp_async16(s0 + so, Ah + aoff);
            cp_async16(s0 + PLANE_BYTES + so, Al + aoff);
            cp_async16(s0 + 2 * PLANE_BYTES + so, Bh + boff);
            cp_async16(s0 + 3 * PLANE_BYTES + so, Bl + boff);
        }
        CP_COMMIT();
    };

    issue(0, 0);
    issue(1, 1);

    float c[16][4];
    #pragma unroll
    for (int i = 0; i < 16; i++)
        #pragma unroll
        for (int j = 0; j < 4; j++) c[i][j] = 0.f;

    int a_row_base = wm * 64 + ((lane >> 3) & 1) * 8 + (lane & 7);
    int a_g_base = (lane >> 4);
    int b_row_base = wn * 32 + ((lane >> 4) & 1) * 8 + (lane & 7);
    int b_g_base = ((lane >> 3) & 1);

    int sidx = 0, pidx = 2;
    for (int kt = 0; kt < NC; kt++) {
        if (kt + 1 < NC) { CP_WAIT(1); } else { CP_WAIT(0); }
        __syncthreads();
        if (kt + 2 < NC) issue(kt + 2, pidx);

        uint32_t sAh = smb + sidx * STAGE_BYTES;
        uint32_t sAl = sAh + PLANE_BYTES;
        uint32_t sBh = sAh + 2 * PLANE_BYTES;
        uint32_t sBl = sAh + 3 * PLANE_BYTES;

        #pragma unroll
        for (int ks = 0; ks < 2; ks++) {
            int ag = ks * 2 + a_g_base;
            int bg = ks * 2 + b_g_base;
            uint32_t bh[4][2], bl[4][2];
            #pragma unroll
            for (int tp = 0; tp < 2; tp++) {
                uint32_t so = sw_off(b_row_base + tp * 16, bg);
                uint32_t r0, r1, r2, r3;
                LDSM4(r0, r1, r2, r3, sBh + so);
                bh[tp * 2][0] = r0;     bh[tp * 2][1] = r1;
                bh[tp * 2 + 1][0] = r2; bh[tp * 2 + 1][1] = r3;
                LDSM4(r0, r1, r2, r3, sBl + so);
                bl[tp * 2][0] = r0;     bl[tp * 2][1] = r1;
                bl[tp * 2 + 1][0] = r2; bl[tp * 2 + 1][1] = r3;
            }
            #pragma unroll
            for (int tm = 0; tm < 4; tm++) {
                uint32_t ah[4], al[4];
                uint32_t so = sw_off(a_row_base + tm * 16, ag);
                LDSM4(ah[0], ah[1], ah[2], ah[3], sAh + so);
                LDSM4(al[0], al[1], al[2], al[3], sAl + so);
                #pragma unroll
                for (int tn = 0; tn < 4; tn++) {
                    MMA_BF16(c[tm * 4 + tn], ah, bh[tn]);
                    MMA_BF16(c[tm * 4 + tn], ah, bl[tn]);
                    MMA_BF16(c[tm * 4 + tn], al, bh[tn]);
                }
            }
        }
        sidx = (sidx + 1 == GSTAGES) ? 0 : sidx + 1;
        pidx = (pidx + 1 == GSTAGES) ? 0 : pidx + 1;
    }

    #pragma unroll
    for (int tm = 0; tm < 4; tm++) {
        #pragma unroll
        for (int half = 0; half < 2; half++) {
            int row = bm + wm * 64 + tm * 16 + (lane >> 2) + half * 8;
            size_t rbase = (size_t)row * N;
            int bb = row >> 10;
            #pragma unroll
            for (int tn = 0; tn < 4; tn++) {
                int col = bn + wn * 32 + tn * 8 + (lane & 3) * 2;
                float d0 = c[tm * 4 + tn][half * 2 + 0];
                float d1 = c[tm * 4 + tn][half * 2 + 1];
                if (MODE == 0) {
                    *(float2*)(Yf + rbase + col) = make_float2(d0, d1);
                } else if (MODE == 4) {
                    bf16 h0, h1, l0, l1;
                    split_f(d0, h0, l0);
                    split_f(d1, h1, l1);
                    *(bf162*)(Yh + rbase + col) = bf162(h0, h1);
                    *(bf162*)(Yl + rbase + col) = bf162(l0, l1);
                } else if (MODE == 2) {
                    float2 bi = *(const float2*)(bias + col);
                    d0 = gelu_tanh(d0 + bi.x);
                    d1 = gelu_tanh(d1 + bi.y);
                    bf16 h0, h1, l0, l1;
                    split_f(d0, h0, l0);
                    split_f(d1, h1, l1);
                    *(bf162*)(Yh + rbase + col) = bf162(h0, h1);
                    *(bf162*)(Yl + rbase + col) = bf162(l0, l1);
                } else {
                    float2 bi = *(const float2*)(bias + col);
                    d0 += bi.x; d1 += bi.y;
                    float2 gv = *(const float2*)(gam + (size_t)bb * 6 * CH + col);
                    float2 xr = *(const float2*)(xres + rbase + col);
                    *(float2*)(Yf + rbase + col) =
                        make_float2(xr.x + d0 * gv.x, xr.y + d1 * gv.y);
                }
            }
        }
    }
}

template <int MODE>
__global__ void __launch_bounds__(256, 2)
gemm_bf3(const bf16* __restrict__ Ah, const bf16* __restrict__ Al,
         const bf16* __restrict__ Bh, const bf16* __restrict__ Bl,
         float* __restrict__ Yf, bf16* __restrict__ Yh, bf16* __restrict__ Yl,
         int M, int N, int K,
         const float* __restrict__ bias, const float* __restrict__ gam,
         const float* __restrict__ xres) {
    extern __shared__ char smraw[];
    gemm_core<MODE>(Ah, Al, Bh, Bl, Yf, Yh, Yl, N, K, bias, gam, xres,
                    smem_u32(smraw), blockIdx.y * 128, blockIdx.x * 128);
}

// merged Q/K/V projection: blockIdx.z selects the (A, B, Y) triple
struct QkvArgs {
    const bf16 *ah[3], *al[3], *bh[3], *bl[3];
    bf16 *yh[3], *yl[3];
};
__global__ void __launch_bounds__(256, 2)
gemm_qkv(QkvArgs a) {
    extern __shared__ char smraw[];
    int z = blockIdx.z;
    gemm_core<4>(a.ah[z], a.al[z], a.bh[z], a.bl[z],
                 nullptr, a.yh[z], a.yl[z], CH, CH,
                 nullptr, nullptr, nullptr,
                 smem_u32(smraw), blockIdx.y * 128, blockIdx.x * 128);
}

// ---------------- FA2-style attention (R8 shape + reg-buffered bias) --------
#define ATT_SMEM (16384 + 2 * 32768)

__global__ void __launch_bounds__(128)
attn_mma(const bf16* __restrict__ Qh, const bf16* __restrict__ Ql,
         const bf16* __restrict__ Kh, const bf16* __restrict__ Kl,
         const bf16* __restrict__ Vh, const bf16* __restrict__ Vl,
         const float* __restrict__ bias,
         bf16* __restrict__ Oh, bf16* __restrict__ Ol) {
    extern __shared__ char smraw[];
    uint32_t smb = smem_u32(smraw);
    int tid = threadIdx.x;
    int lane = tid & 31, w = tid >> 5;
    int bh = blockIdx.x;
    int b = bh >> 4, h = bh & 15;
    int q0 = blockIdx.y * 64;

    {
        const bf16* qp[2] = {Qh, Ql};
        #pragma unroll
        for (int it = 0; it < 8; it++) {
            int pl = it >> 2;
            int row = (it & 3) * 16 + (tid >> 3);
            int g = tid & 7;
            cp_async16(smb + pl * 8192 + sw128(row, g),
                       qp[pl] + (size_t)(b * SEQ + q0 + row) * CH + h * DH + g * 8);
        }
    }
    auto issue_tile = [&](int kt) {
        uint32_t st = smb + 16384 + (kt & 1) * 32768;
        const bf16* pp[4] = {Kh, Kl, Vh, Vl};
        #pragma unroll
        for (int it = 0; it < 16; it++) {
            int pl = it >> 2;
            int row = (it & 3) * 16 + (tid >> 3);
            int g = tid & 7;
            cp_async16(st + pl * 8192 + sw128(row, g),
                       pp[pl] + (size_t)(b * SEQ + kt * 64 + row) * CH + h * DH + g * 8);
        }
    };
    issue_tile(0);
    CP_COMMIT();

    const float* bp0 = bias +
        ((size_t)(b * NH + h) * SEQ + q0 + w * 16 + (lane >> 2)) * SEQ + (lane & 3) * 2;

    // preload bias for tile 0 into registers
    float2 bufA[8], bufB[8];
    #pragma unroll
    for (int n = 0; n < 8; n++) {
        bufA[n] = *(const float2*)(bp0 + n * 8);
        bufB[n] = *(const float2*)(bp0 + (size_t)8 * SEQ + n * 8);
    }

    CP_WAIT(0);
    __syncthreads();

    uint32_t qhf[4][4], qlf[4][4];
    {
        int qrow = w * 16 + (lane & 15);
        #pragma unroll
        for (int ks = 0; ks < 4; ks++) {
            uint32_t so = sw128(qrow, ks * 2 + (lane >> 4));
            LDSM4(qhf[ks][0], qhf[ks][1], qhf[ks][2], qhf[ks][3], smb + so);
            LDSM4(qlf[ks][0], qlf[ks][1], qlf[ks][2], qlf[ks][3], smb + 8192 + so);
        }
    }

    float o[8][4];
    #pragma unroll
    for (int n = 0; n < 8; n++)
        #pragma unroll
        for (int j = 0; j < 4; j++) o[n][j] = 0.f;
    float miA = -1e30f, miB = -1e30f, liA = 0.f, liB = 0.f;

    for (int kt = 0; kt < 16; kt++) {
        if (kt + 1 < 16) { issue_tile(kt + 1); CP_COMMIT(); }

        uint32_t sKh = smb + 16384 + (kt & 1) * 32768;
        uint32_t sKl = sKh + 8192;
        uint32_t sVh = sKh + 16384;
        uint32_t sVl = sKh + 24576;

        float s[8][4];
        #pragma unroll
        for (int n = 0; n < 8; n++)
            #pragma unroll
            for (int j = 0; j < 4; j++) s[n][j] = 0.f;

        int krow_base = ((lane >> 4) & 1) * 8 + (lane & 7);
        int kg_base = (lane >> 3) & 1;
        #pragma unroll
        for (int ks = 0; ks < 4; ks++) {
            int kg = ks * 2 + kg_base;
            #pragma unroll
            for (int np = 0; np < 4; np++) {
                uint32_t so = sw128(np * 16 + krow_base, kg);
                uint32_t h0, h1, h2, h3, l0, l1, l2, l3;
                LDSM4(h0, h1, h2, h3, sKh + so);
                LDSM4(l0, l1, l2, l3, sKl + so);
                MMA_BF16_2(s[np * 2], qhf[ks], h0, h1);
                MMA_BF16_2(s[np * 2], qlf[ks], h0, h1);
                MMA_BF16_2(s[np * 2], qhf[ks], l0, l1);
                MMA_BF16_2(s[np * 2 + 1], qhf[ks], h2, h3);
                MMA_BF16_2(s[np * 2 + 1], qlf[ks], h2, h3);
                MMA_BF16_2(s[np * 2 + 1], qhf[ks], l2, l3);
            }
        }

        // consume preloaded bias for this tile
        #pragma unroll
        for (int n = 0; n < 8; n++) {
            s[n][0] = fmaf(s[n][0], ASCALE, bufA[n].x);
            s[n][1] = fmaf(s[n][1], ASCALE, bufA[n].y);
            s[n][2] = fmaf(s[n][2], ASCALE, bufB[n].x);
            s[n][3] = fmaf(s[n][3], ASCALE, bufB[n].y);
        }
        // issue bias loads for the next tile (latency hidden below)
        if (kt + 1 < 16) {
            const float* bp = bp0 + (kt + 1) * 64;
            #pragma unroll
            for (int n = 0; n < 8; n++) {
                bufA[n] = *(const float2*)(bp + n * 8);
                bufB[n] = *(const float2*)(bp + (size_t)8 * SEQ + n * 8);
            }
        }

        float mA = -1e30f, mB = -1e30f;
        #pragma unroll
        for (int n = 0; n < 8; n++) {
            mA = fmaxf(mA, fmaxf(s[n][0], s[n][1]));
            mB = fmaxf(mB, fmaxf(s[n][2], s[n][3]));
        }
        mA = fmaxf(mA, __shfl_xor_sync(0xffffffffu, mA, 1));
        mA = fmaxf(mA, __shfl_xor_sync(0xffffffffu, mA, 2));
        mB = fmaxf(mB, __shfl_xor_sync(0xffffffffu, mB, 1));
        mB = fmaxf(mB, __shfl_xor_sync(0xffffffffu, mB, 2));
        float mnA = fmaxf(miA, mA), mnB = fmaxf(miB, mB);
        float corrA = __expf(miA - mnA), corrB = __expf(miB - mnB);
        miA = mnA; miB = mnB;
        float rsA = 0.f, rsB = 0.f;
        #pragma unroll
        for (int n = 0; n < 8; n++) {
            s[n][0] = __expf(s[n][0] - mnA);
            s[n][1] = __expf(s[n][1] - mnA);
            s[n][2] = __expf(s[n][2] - mnB);
            s[n][3] = __expf(s[n][3] - mnB);
            rsA += s[n][0] + s[n][1];
            rsB += s[n][2] + s[n][3];
        }
        rsA += __shfl_xor_sync(0xffffffffu, rsA, 1);
        rsA += __shfl_xor_sync(0xffffffffu, rsA, 2);
        rsB += __shfl_xor_sync(0xffffffffu, rsB, 1);
        rsB += __shfl_xor_sync(0xffffffffu, rsB, 2);
        liA = liA * corrA + rsA;
        liB = liB * corrB + rsB;
        #pragma unroll
        for (int n = 0; n < 8; n++) {
            o[n][0] *= corrA; o[n][1] *= corrA;
            o[n][2] *= corrB; o[n][3] *= corrB;
        }

        int vrow_base = ((lane >> 3) & 1) * 8 + (lane & 7);
        int vg_base = (lane >> 4) & 1;
        #pragma unroll
        for (int kk = 0; kk < 4; kk++) {
            uint32_t pah[4], pal[4];
            #pragma unroll
            for (int q = 0; q < 2; q++) {
                int nf = kk * 2 + q;
                float p0 = s[nf][0], p1 = s[nf][1], p2 = s[nf][2], p3 = s[nf][3];
                float h0 = __bfloat162float(__float2bfloat16_rn(p0));
                float h1 = __bfloat162float(__float2bfloat16_rn(p1));
                float h2 = __bfloat162float(__float2bfloat16_rn(p2));
                float h3 = __bfloat162float(__float2bfloat16_rn(p3));
                pah[q * 2 + 0] = pack_bf2(h0, h1);
                pah[q * 2 + 1] = pack_bf2(h2, h3);
                pal[q * 2 + 0] = pack_bf2(p0 - h0, p1 - h1);
                pal[q * 2 + 1] = pack_bf2(p2 - h2, p3 - h3);
            }
            #pragma unroll
            for (int dp = 0; dp < 4; dp++) {
                uint32_t so = sw128(kk * 16 + vrow_base, dp * 2 + vg_base);
                uint32_t r0, r1, r2, r3;
                LDSM4T(r0, r1, r2, r3, sVh + so);
                MMA_BF16_2(o[dp * 2], pah, r0, r1);
                MMA_BF16_2(o[dp * 2], pal, r0, r1);
                MMA_BF16_2(o[dp * 2 + 1], pah, r2, r3);
                MMA_BF16_2(o[dp * 2 + 1], pal, r2, r3);
                LDSM4T(r0, r1, r2, r3, sVl + so);
                MMA_BF16_2(o[dp * 2], pah, r0, r1);
                MMA_BF16_2(o[dp * 2 + 1], pah, r2, r3);
            }
        }

        if (kt + 1 < 16) { CP_WAIT(0); __syncthreads(); }
    }

    float invA = 1.0f / liA, invB = 1.0f / liB;
    size_t rowA = (size_t)(b * SEQ + q0 + w * 16 + (lane >> 2));
    #pragma unroll
    for (int n = 0; n < 8; n++) {
        int col = h * DH + n * 8 + (lane & 3) * 2;
        float f0 = o[n][0] * invA, f1 = o[n][1] * invA;
        float f2 = o[n][2] * invB, f3 = o[n][3] * invB;
        bf16 h0, h1, h2, h3, l0, l1, l2, l3;
        split_f(f0, h0, l0); split_f(f1, h1, l1);
        split_f(f2, h2, l2); split_f(f3, h3, l3);
        *(bf162*)(Oh + rowA * CH + col) = bf162(h0, h1);
        *(bf162*)(Ol + rowA * CH + col) = bf162(l0, l1);
        *(bf162*)(Oh + (rowA + 8) * CH + col) = bf162(h2, h3);
        *(bf162*)(Ol + (rowA + 8) * CH + col) = bf162(l2, l3);
    }
}

// ---------------- launch ------------------------------------------------------
extern "C" void kernel_launch(void* const* d_in, const int* in_sizes, int n_in,
                              void* d_out, int out_size) {
    const float* x         = (const float*)d_in[0];
    const float* context   = (const float*)d_in[1];
    const float* cond_BD   = (const float*)d_in[2];
    const float* attn_bias = (const float*)d_in[3];
    const float* ada_gss   = (const float*)d_in[4];
    const float* Wq        = (const float*)d_in[5];
    const float* Wk        = (const float*)d_in[6];
    const float* Wv        = (const float*)d_in[7];
    const float* Wo        = (const float*)d_in[8];
    const float* bo        = (const float*)d_in[9];
    const float* W1        = (const float*)d_in[10];
    const float* b1        = (const float*)d_in[11];
    const float* W2        = (const float*)d_in[12];
    const float* b2        = (const float*)d_in[13];
    float* out = (float*)d_out;

    float *g_p, *x1_p;
    cudaGetSymbolAddress((void**)&g_p, g_buf);
    cudaGetSymbolAddress((void**)&x1_p, x1_buf);

    bf16 *wqh, *wql, *wkh, *wkl, *wvh, *wvl, *woh, *wol;
    bf16 *w1h, *w1l, *w2h, *w2l, *ch_, *cl_, *mh, *ml, *aoh, *aol, *hh, *hl;
    bf16 *qh, *ql, *kh, *kl, *vh, *vl;
    cudaGetSymbolAddress((void**)&wqh, wq_h); cudaGetSymbolAddress((void**)&wql, wq_l);
    cudaGetSymbolAddress((void**)&wkh, wk_h); cudaGetSymbolAddress((void**)&wkl, wk_l);
    cudaGetSymbolAddress((void**)&wvh, wv_h); cudaGetSymbolAddress((void**)&wvl, wv_l);
    cudaGetSymbolAddress((void**)&woh, wo_h); cudaGetSymbolAddress((void**)&wol, wo_l);
    cudaGetSymbolAddress((void**)&w1h, w1_h); cudaGetSymbolAddress((void**)&w1l, w1_l);
    cudaGetSymbolAddress((void**)&w2h, w2_h); cudaGetSymbolAddress((void**)&w2l, w2_l);
    cudaGetSymbolAddress((void**)&ch_, ctx_h); cudaGetSymbolAddress((void**)&cl_, ctx_l);
    cudaGetSymbolAddress((void**)&mh, mod_h);  cudaGetSymbolAddress((void**)&ml, mod_l);
    cudaGetSymbolAddress((void**)&aoh, ao_h);  cudaGetSymbolAddress((void**)&aol, ao_l);
    cudaGetSymbolAddress((void**)&hh, hb_h);   cudaGetSymbolAddress((void**)&hl, hb_l);
    cudaGetSymbolAddress((void**)&qh, q_h);    cudaGetSymbolAddress((void**)&ql, q_l);
    cudaGetSymbolAddress((void**)&kh, k_h);    cudaGetSymbolAddress((void**)&kl, k_l);
    cudaGetSymbolAddress((void**)&vh, v_h);    cudaGetSymbolAddress((void**)&vl, v_l);

    cudaFuncSetAttribute(attn_mma,
                         cudaFuncAttributeMaxDynamicSharedMemorySize, ATT_SMEM);
    cudaFuncSetAttribute(gemm_qkv,
                         cudaFuncAttributeMaxDynamicSharedMemorySize, GEMM_SMEM);
    cudaFuncSetAttribute(gemm_bf3<1>,
                         cudaFuncAttributeMaxDynamicSharedMemorySize, GEMM_SMEM);
    cudaFuncSetAttribute(gemm_bf3<2>,
                         cudaFuncAttributeMaxDynamicSharedMemorySize, GEMM_SMEM);
    cudaFuncSetAttribute(gemm_bf3<3>,
                         cudaFuncAttributeMaxDynamicSharedMemorySize, GEMM_SMEM);

    add_params_kernel<<<24, 1024>>>(ada_gss, cond_BD);                           // 0
    ln_mod_kernel<<<NROWS, 256>>>(x, mh, ml, 2, 4);                              // 1

    // one launch for all seven fp32 -> bf16 hi/lo splits
    Split7Args s7;
    s7.src[0] = context; s7.hi[0] = ch_; s7.lo[0] = cl_; s7.n4[0] = NROWS * CH / 4;
    s7.src[1] = W1;      s7.hi[1] = w1h; s7.lo[1] = w1l; s7.n4[1] = FFNDIM * CH / 4;
    s7.src[2] = W2;      s7.hi[2] = w2h; s7.lo[2] = w2l; s7.n4[2] = FFNDIM * CH / 4;
    s7.src[3] = Wq;      s7.hi[3] = wqh; s7.lo[3] = wql; s7.n4[3] = CH * CH / 4;
    s7.src[4] = Wk;      s7.hi[4] = wkh; s7.lo[4] = wkl; s7.n4[4] = CH * CH / 4;
    s7.src[5] = Wv;      s7.hi[5] = wvh; s7.lo[5] = wvl; s7.n4[5] = CH * CH / 4;
    s7.src[6] = Wo;      s7.hi[6] = woh; s7.lo[6] = wol; s7.n4[6] = CH * CH / 4;
    split7_kernel<<<dim3(NROWS * CH / 4096, 7), 256>>>(s7);                      // 2

    QkvArgs qa;
    qa.ah[0] = mh;  qa.al[0] = ml;  qa.bh[0] = wqh; qa.bl[0] = wql;
    qa.yh[0] = qh;  qa.yl[0] = ql;
    qa.ah[1] = ch_; qa.al[1] = cl_; qa.bh[1] = wkh; qa.bl[1] = wkl;
    qa.yh[1] = kh;  qa.yl[1] = kl;
    qa.ah[2] = ch_; qa.al[2] = cl_; qa.bh[2] = wvh; qa.bl[2] = wvl;
    qa.yh[2] = vh;  qa.yl[2] = vl;
    gemm_qkv<<<dim3(8, 32, 3), 256, GEMM_SMEM>>>(qa);                            // 3

    attn_mma<<<dim3(NB * NH, SEQ / 64), 128, ATT_SMEM>>>(qh, ql, kh, kl, vh, vl,
                                                         attn_bias, aoh, aol);   // 4

    gemm_bf3<1><<<dim3(8, 32), 256, GEMM_SMEM>>>(aoh, aol, woh, wol, x1_p,
                                                 nullptr, nullptr,
                                                 NROWS, CH, CH,
                                                 bo, g_p + 0 * CH, x);           // 5

    ln_mod_kernel<<<NROWS, 256>>>(x1_p, mh, ml, 3, 5);                           // 6

    gemm_bf3<2><<<dim3(32, 32), 256, GEMM_SMEM>>>(mh, ml, w1h, w1l, nullptr,
                                                  hh, hl,
                                                  NROWS, FFNDIM, CH,
                                                  b1, nullptr, nullptr);         // 7

    gemm_bf3<3><<<dim3(8, 32), 256, GEMM_SMEM>>>(hh, hl, w2h, w2l, out,
                                                 nullptr, nullptr,
                                                 NROWS, CH, FFNDIM,
                                                 b2, g_p + 1 * CH, x1_p);        // 8
}